// round 15
// baseline (speedup 1.0000x reference)
#include <cuda_runtime.h>
#include <cuda_bf16.h>
#include <cstdint>

// ---------------------------------------------------------------------------
// Arch dispatch: tcgen05 only on arch/family-specific targets (field-proven)
// ---------------------------------------------------------------------------
#if defined(__CUDA_ARCH_FEAT_SM103_ALL) || defined(__CUDA_ARCH_FEAT_SM100_ALL) || \
    (defined(__CUDA_ARCH_FAMILY_SPECIFIC__) && (__CUDA_ARCH_FAMILY_SPECIFIC__ == 1030 || __CUDA_ARCH_FAMILY_SPECIFIC__ == 1000)) || \
    (defined(__CUDA_ARCH_SPECIFIC__) && (__CUDA_ARCH_SPECIFIC__ == 1030 || __CUDA_ARCH_SPECIFIC__ == 1000))
#define USE_TC 1
#else
#define USE_TC 0
#endif

// ---------------------------------------------------------------------------
// Shapes
// ---------------------------------------------------------------------------
#define BS      32
#define NUM_R   10
#define SL_Q    20
#define SL_H    40
#define WE      300
#define LSTM    1024
#define BILSTM  2048
#define FEATD   600

#define MQ (BS * SL_Q)          // 640
#define MH (BS * NUM_R * SL_H)  // 12800
#define KW (BILSTM / 2)         // 1024 packed bf16x2 words per row

// ---------------------------------------------------------------------------
// Scratch (device globals)
// ---------------------------------------------------------------------------
__device__ float g_qfeat[MQ * LSTM];
__device__ float g_hfeat[MH * LSTM];
__device__ float g_topic[BS * NUM_R * SL_Q * WE];
__device__ float g_feat [MQ * FEATD];

__device__ uint32_t g_xq_h[MQ * KW],  g_xq_l[MQ * KW];
__device__ uint32_t g_xh_h[MH * KW],  g_xh_l[MH * KW];
__device__ uint32_t g_wqy_h[LSTM * KW], g_wqy_l[LSTM * KW];
__device__ uint32_t g_wqg_h[LSTM * KW], g_wqg_l[LSTM * KW];
__device__ uint32_t g_why_h[LSTM * KW], g_why_l[LSTM * KW];
__device__ uint32_t g_whg_h[LSTM * KW], g_whg_l[LSTM * KW];

// ---------------------------------------------------------------------------
// Helpers
// ---------------------------------------------------------------------------
__device__ __forceinline__ float leaky(float x) {
    return x >= 0.f ? x : 0.01f * x;
}

__device__ __forceinline__ void split2(float a, float b, uint32_t& hi, uint32_t& lo) {
    __nv_bfloat16 ha = __float2bfloat16(a);
    __nv_bfloat16 hb = __float2bfloat16(b);
    __nv_bfloat16 la = __float2bfloat16(a - __bfloat162float(ha));
    __nv_bfloat16 lb = __float2bfloat16(b - __bfloat162float(hb));
    union { __nv_bfloat162 v; uint32_t u; } ph, pl;
    ph.v.x = ha; ph.v.y = hb; pl.v.x = la; pl.v.y = lb;
    hi = ph.u; lo = pl.u;
}

__device__ __forceinline__ void cpasync16(uint32_t dst, const void* src) {
    asm volatile("cp.async.cg.shared.global [%0], [%1], 16;"
                 :: "r"(dst), "l"(src) : "memory");
}

__device__ __forceinline__ void mma_bf16(float c[4], const uint32_t a[4],
                                         uint32_t b0, uint32_t b1) {
    asm volatile(
        "mma.sync.aligned.m16n8k16.row.col.f32.bf16.bf16.f32 "
        "{%0,%1,%2,%3},{%4,%5,%6,%7},{%8,%9},{%0,%1,%2,%3};"
        : "+f"(c[0]), "+f"(c[1]), "+f"(c[2]), "+f"(c[3])
        : "r"(a[0]), "r"(a[1]), "r"(a[2]), "r"(a[3]), "r"(b0), "r"(b1));
}

__device__ __forceinline__ void ldsm_x4(uint32_t& r0, uint32_t& r1,
                                        uint32_t& r2, uint32_t& r3, uint32_t addr) {
    asm volatile("ldmatrix.sync.aligned.m8n8.x4.shared.b16 {%0,%1,%2,%3}, [%4];"
                 : "=r"(r0), "=r"(r1), "=r"(r2), "=r"(r3) : "r"(addr));
}

#if USE_TC
__device__ __forceinline__ uint32_t elect_one() {
    uint32_t pred;
    asm volatile("{\n\t.reg .pred p;\n\telect.sync _|p, 0xFFFFFFFF;\n\t"
                 "selp.b32 %0, 1, 0, p;\n\t}" : "=r"(pred));
    return pred;
}
__device__ __forceinline__ void mbar_init(uint32_t mbar, uint32_t cnt) {
    asm volatile("mbarrier.init.shared.b64 [%0], %1;" :: "r"(mbar), "r"(cnt) : "memory");
}
__device__ __forceinline__ void mbar_inval(uint32_t mbar) {
    asm volatile("mbarrier.inval.shared.b64 [%0];" :: "r"(mbar) : "memory");
}
__device__ __forceinline__ void mbar_wait(uint32_t mbar, uint32_t parity) {
    asm volatile(
        "{\n\t.reg .pred P;\n\t"
        "WAIT_%=:\n\t"
        "mbarrier.try_wait.parity.acquire.cta.shared::cta.b64 P, [%0], %1, 0x989680;\n\t"
        "@P bra DONE_%=;\n\t"
        "bra WAIT_%=;\n\t"
        "DONE_%=:\n\t}"
        :: "r"(mbar), "r"(parity) : "memory");
}
__device__ __forceinline__ uint64_t sdesc(uint32_t addr) {
    return (2ull << 61) | (1ull << 46) | (64ull << 32) | (1ull << 16)
         | ((uint64_t)(addr >> 4) & 0x3FFF);
}
__device__ __forceinline__ void mma_ss(uint32_t d, uint64_t a, uint64_t b,
                                       uint32_t idesc, uint32_t en) {
    asm volatile(
        "{\n\t.reg .pred p;\n\tsetp.ne.u32 p, %4, 0;\n\t"
        "tcgen05.mma.cta_group::1.kind::f16 [%0], %1, %2, %3, {%5, %5, %5, %5}, p;\n\t}"
        :: "r"(d), "l"(a), "l"(b), "r"(idesc), "r"(en), "r"(0u)
        : "memory");
}
__device__ __forceinline__ void ldtm_x32(uint32_t* r, uint32_t a) {
    asm volatile(
        "tcgen05.ld.sync.aligned.32x32b.x32.b32 "
        "{%0,%1,%2,%3,%4,%5,%6,%7,%8,%9,%10,%11,%12,%13,%14,%15,"
        "%16,%17,%18,%19,%20,%21,%22,%23,%24,%25,%26,%27,%28,%29,%30,%31}, [%32];"
        : "=r"(r[0]),  "=r"(r[1]),  "=r"(r[2]),  "=r"(r[3]),
          "=r"(r[4]),  "=r"(r[5]),  "=r"(r[6]),  "=r"(r[7]),
          "=r"(r[8]),  "=r"(r[9]),  "=r"(r[10]), "=r"(r[11]),
          "=r"(r[12]), "=r"(r[13]), "=r"(r[14]), "=r"(r[15]),
          "=r"(r[16]), "=r"(r[17]), "=r"(r[18]), "=r"(r[19]),
          "=r"(r[20]), "=r"(r[21]), "=r"(r[22]), "=r"(r[23]),
          "=r"(r[24]), "=r"(r[25]), "=r"(r[26]), "=r"(r[27]),
          "=r"(r[28]), "=r"(r[29]), "=r"(r[30]), "=r"(r[31])
        : "r"(a));
}
#endif  // USE_TC

// ---------------------------------------------------------------------------
// Precompute (fused): X_q and X_h -> packed kpair bf16 hi/lo words (proven)
// ---------------------------------------------------------------------------
__global__ __launch_bounds__(256)
void split_x_all(const float* __restrict__ xq, uint32_t* __restrict__ qhi,
                 uint32_t* __restrict__ qlo,
                 const float* __restrict__ xh, uint32_t* __restrict__ hhi,
                 uint32_t* __restrict__ hlo) {
    const int n4q = MQ * BILSTM / 4;
    const int n4h = MH * BILSTM / 4;
    int i = blockIdx.x * 256 + threadIdx.x;
    const float* x; uint32_t *hi, *lo; int j;
    if (i < n4q) { x = xq; hi = qhi; lo = qlo; j = i; }
    else if (i < n4q + n4h) { x = xh; hi = hhi; lo = hlo; j = i - n4q; }
    else return;
    float4 v = ((const float4*)x)[j];
    uint32_t h0, l0, h1, l1;
    split2(v.x, v.y, h0, l0);
    split2(v.z, v.w, h1, l1);
    ((uint2*)hi)[j] = make_uint2(h0, h1);
    ((uint2*)lo)[j] = make_uint2(l0, l1);
}

// ---------------------------------------------------------------------------
// Precompute (fused): 4 weights -> transposed packed [1024][KW] hi/lo (proven)
// ---------------------------------------------------------------------------
__global__ __launch_bounds__(256)
void split_wt_all(const float* __restrict__ W0, uint32_t* __restrict__ h0p, uint32_t* __restrict__ l0p,
                  const float* __restrict__ W1, uint32_t* __restrict__ h1p, uint32_t* __restrict__ l1p,
                  const float* __restrict__ W2, uint32_t* __restrict__ h2p, uint32_t* __restrict__ l2p,
                  const float* __restrict__ W3, uint32_t* __restrict__ h3p, uint32_t* __restrict__ l3p) {
    const float* W; uint32_t *thi, *tlo;
    switch (blockIdx.z) {
        case 0:  W = W0; thi = h0p; tlo = l0p; break;
        case 1:  W = W1; thi = h1p; tlo = l1p; break;
        case 2:  W = W2; thi = h2p; tlo = l2p; break;
        default: W = W3; thi = h3p; tlo = l3p; break;
    }
    __shared__ float t[32][33];
    int k0 = blockIdx.x * 32, n0 = blockIdx.y * 32;
    int tx = threadIdx.x & 31, ty = threadIdx.x >> 5;
#pragma unroll
    for (int j = 0; j < 4; j++)
        t[ty + 8 * j][tx] = W[(size_t)(k0 + ty + 8 * j) * LSTM + n0 + tx];
    __syncthreads();
    for (int w = threadIdx.x; w < 512; w += 256) {
        int nn = w >> 4;
        int kp = w & 15;
        uint32_t h, l;
        split2(t[2 * kp][nn], t[2 * kp + 1][nn], h, l);
        size_t o = (size_t)(n0 + nn) * KW + (k0 >> 1) + kp;
        thi[o] = h;
        tlo[o] = l;
    }
}

// ---------------------------------------------------------------------------
// Gated transform: out = tanh(X@Wy+by) * leaky_relu(X@Wg+bg), 3xBF16.
// Path A (tcgen05): REORDERED pipeline — per iteration:
//   wait chunk c -> sync -> issue MMA(c)+commit -> wait commit(c-1) (already
//   done: in-order queue, MMA(c) still running) -> issue load(c+1), which
//   overlaps MMA(c). Steady state = max(load, MMA) instead of load + MMA.
// Path B (legacy HMMA fallback): R12 proven, verbatim.
// ---------------------------------------------------------------------------
#define TBM 128
#define TBN 128
#define TKC 64
#define NCHUNK (BILSTM / TKC)          // 32
#define CH_BYTES 98304
#define SM_CTRL 1024
#define GG_SMEM (SM_CTRL + 2 * CH_BYTES)
#define IDESC_GG 0x8200490u

__global__ __launch_bounds__(256, 1)
void gated_gemm_all(const uint32_t* __restrict__ qXh, const uint32_t* __restrict__ qXl,
                    const uint32_t* __restrict__ qWyh, const uint32_t* __restrict__ qWyl,
                    const uint32_t* __restrict__ qWgh, const uint32_t* __restrict__ qWgl,
                    const float* __restrict__ qby, const float* __restrict__ qbg,
                    float* __restrict__ qout,
                    const uint32_t* __restrict__ hXh, const uint32_t* __restrict__ hXl,
                    const uint32_t* __restrict__ hWyh, const uint32_t* __restrict__ hWyl,
                    const uint32_t* __restrict__ hWgh, const uint32_t* __restrict__ hWgl,
                    const float* __restrict__ hby, const float* __restrict__ hbg,
                    float* __restrict__ hout) {
    extern __shared__ char smem[];
    const uint32_t smem_base = (uint32_t)__cvta_generic_to_shared(smem);
    const int tid  = threadIdx.x;
    const int warp = tid >> 5;
    const int lane = tid & 31;
    const int n0 = blockIdx.x * TBN;

    const bool isq = (blockIdx.y < 5);
    const int m0 = isq ? blockIdx.y * TBM : (blockIdx.y - 5) * TBM;
    const uint32_t* Xh  = isq ? qXh  : hXh;
    const uint32_t* Xl  = isq ? qXl  : hXl;
    const uint32_t* Wyh = isq ? qWyh : hWyh;
    const uint32_t* Wyl = isq ? qWyl : hWyl;
    const uint32_t* Wgh = isq ? qWgh : hWgh;
    const uint32_t* Wgl = isq ? qWgl : hWgl;
    const float* by = isq ? qby : hby;
    const float* bg = isq ? qbg : hbg;
    float* out = isq ? qout : hout;

    auto load_chunk = [&](int c) {
        const uint32_t bb = smem_base + SM_CTRL + (uint32_t)(c & 1) * CH_BYTES;
        const int kw0 = c * (TKC / 2);
#pragma unroll
        for (int i = 0; i < 24; i++) {
            const int reg = i >> 2;
            const int v   = tid + (i & 3) * 256;
            const int row = v >> 3, seg = v & 7;
            const uint32_t* s; int rb; uint32_t doff;
            if      (reg == 0) { s = Xh;  rb = m0; doff = 0; }
            else if (reg == 1) { s = Xl;  rb = m0; doff = 16384; }
            else if (reg == 2) { s = Wyh; rb = n0; doff = 32768; }
            else if (reg == 3) { s = Wyl; rb = n0; doff = 49152; }
            else if (reg == 4) { s = Wgh; rb = n0; doff = 65536; }
            else               { s = Wgl; rb = n0; doff = 81920; }
            const void* src = s + (size_t)(rb + row) * KW + kw0 + seg * 4;
            uint32_t bo = (uint32_t)(row * 128 + seg * 16);
            cpasync16(bb + doff + (bo ^ ((bo >> 3) & 0x70)), src);
        }
        asm volatile("cp.async.commit_group;" ::: "memory");
    };

#if USE_TC
    // ---------------- tcgen05 path: reordered overlap pipeline -------------
    const uint32_t mb0 = smem_base + 16, mb1 = smem_base + 24;
    if (warp == 0)
        asm volatile("tcgen05.alloc.cta_group::1.sync.aligned.shared::cta.b32 [%0], %1;"
                     :: "r"(smem_base), "r"(256u) : "memory");
    if (tid == 0) { mbar_init(mb0, 1); mbar_init(mb1, 1); }
    __syncthreads();
    uint32_t tmem;
    asm volatile("ld.shared.b32 %0, [%1];" : "=r"(tmem) : "r"(smem_base));
    const uint32_t tY = tmem, tG = tmem + 128;

    int ph0 = 0, ph1 = 0;
    load_chunk(0);
    for (int c = 0; c < NCHUNK; c++) {
        // chunk c is the only pending cp.async group — wait it
        asm volatile("cp.async.wait_group 0;" ::: "memory");
        asm volatile("tcgen05.fence::before_thread_sync;" ::: "memory");
        asm volatile("fence.proxy.async.shared::cta;" ::: "memory");
        __syncthreads();

        // issue MMA(c) from buffer c&1
        if (warp == 0) {
            asm volatile("tcgen05.fence::after_thread_sync;" ::: "memory");
            if (elect_one()) {
                const uint32_t bb = smem_base + SM_CTRL + (uint32_t)(c & 1) * CH_BYTES;
                uint64_t dAh = sdesc(bb),         uAl = 0;
                uint64_t dAl = sdesc(bb + 16384);
                uint64_t dYh = sdesc(bb + 32768), dYl = sdesc(bb + 49152);
                uint64_t dGh = sdesc(bb + 65536), dGl = sdesc(bb + 81920);
                (void)uAl;
#pragma unroll
                for (int s = 0; s < 4; s++) {
                    uint64_t o = (uint64_t)(s * 2);
                    uint32_t en0 = (c == 0 && s == 0) ? 0u : 1u;
                    mma_ss(tY, dAh + o, dYh + o, IDESC_GG, en0);
                    mma_ss(tY, dAh + o, dYl + o, IDESC_GG, 1u);
                    mma_ss(tY, dAl + o, dYh + o, IDESC_GG, 1u);
                    mma_ss(tG, dAh + o, dGh + o, IDESC_GG, en0);
                    mma_ss(tG, dAh + o, dGl + o, IDESC_GG, 1u);
                    mma_ss(tG, dAl + o, dGh + o, IDESC_GG, 1u);
                }
                asm volatile(
                    "tcgen05.commit.cta_group::1.mbarrier::arrive::one.shared::cluster.b64 [%0];"
                    :: "r"((c & 1) ? mb1 : mb0) : "memory");
            }
        }

        // now prefetch chunk c+1 into buffer (c+1)&1, which MMA(c-1) used —
        // wait its commit (already complete: queue is in-order, MMA(c) running)
        if (c + 1 < NCHUNK) {
            if (c >= 1) {
                if ((c - 1) & 1) { mbar_wait(mb1, (uint32_t)ph1); ph1 ^= 1; }
                else             { mbar_wait(mb0, (uint32_t)ph0); ph0 ^= 1; }
            }
            load_chunk(c + 1);   // overlaps MMA(c) execution
        }
    }
    // final: wait MMA(31) (odd -> mb1)
    mbar_wait(mb1, (uint32_t)ph1);
    asm volatile("tcgen05.fence::after_thread_sync;" ::: "memory");

    float* ep = (float*)(smem + SM_CTRL);   // 128 x 129 staging
    if (warp < 4) {
        const int m = warp * 32 + lane;
#pragma unroll
        for (int s = 0; s < 4; s++) {
            uint32_t ry[32], rg[32];
            ldtm_x32(ry, tY + s * 32);
            ldtm_x32(rg, tG + s * 32);
            asm volatile("tcgen05.wait::ld.sync.aligned;" ::: "memory");
#pragma unroll
            for (int cc = 0; cc < 32; cc++) {
                int nn = n0 + s * 32 + cc;
                float yv = __uint_as_float(ry[cc]) + by[nn];
                float gv = __uint_as_float(rg[cc]) + bg[nn];
                ep[m * 129 + s * 32 + cc] = tanhf(yv) * leaky(gv);
            }
        }
    }
    __syncthreads();
    for (int i = tid; i < TBM * TBN; i += 256) {
        int row = i >> 7, col = i & 127;
        out[(size_t)(m0 + row) * LSTM + n0 + col] = ep[row * 129 + col];
    }
    __syncthreads();
    if (tid == 0) { mbar_inval(mb0); mbar_inval(mb1); }
    __syncthreads();
    if (warp == 0) {
        asm volatile("tcgen05.relinquish_alloc_permit.cta_group::1.sync.aligned;");
        asm volatile("tcgen05.dealloc.cta_group::1.sync.aligned.b32 %0, %1;"
                     :: "r"(tmem), "r"(256u));
    }
#else
    // ---------------- legacy HMMA fallback (R12 proven, verbatim) ----------
    const int wm = (warp >> 2) * 64;
    const int wn = (warp & 3) * 32;

    int rowA[4], swzA[4];
#pragma unroll
    for (int mt = 0; mt < 4; mt++) {
        rowA[mt] = wm + 16 * mt + (lane & 15);
        swzA[mt] = rowA[mt] & 7;
    }
    const int kselA = lane >> 4;
    int rowB[2], swzB[2];
#pragma unroll
    for (int ntp = 0; ntp < 2; ntp++) {
        rowB[ntp] = wn + 16 * ntp + (lane & 7) + ((lane & 16) >> 1);
        swzB[ntp] = rowB[ntp] & 7;
    }
    const int kselB = (lane >> 3) & 1;

    float accY[4][4][4] = {};
    float accG[4][4][4] = {};

    load_chunk(0);
    for (int c = 0; c < NCHUNK; c++) {
        if (c + 1 < NCHUNK) {
            load_chunk(c + 1);
            asm volatile("cp.async.wait_group 1;" ::: "memory");
        } else {
            asm volatile("cp.async.wait_group 0;" ::: "memory");
        }
        __syncthreads();
        const uint32_t bb = smem_base + SM_CTRL + (uint32_t)(c & 1) * CH_BYTES;

#pragma unroll
        for (int ks = 0; ks < 4; ks++) {
            const uint32_t gA = (uint32_t)(2 * ks + kselA);
            const uint32_t gB = (uint32_t)(2 * ks + kselB);
            uint32_t ah[4][4], al[4][4];
#pragma unroll
            for (int mt = 0; mt < 4; mt++) {
                uint32_t off = (uint32_t)(rowA[mt] * 128) + ((gA ^ (uint32_t)swzA[mt]) << 4);
                ldsm_x4(ah[mt][0], ah[mt][1], ah[mt][2], ah[mt][3], bb + off);
                ldsm_x4(al[mt][0], al[mt][1], al[mt][2], al[mt][3], bb + 16384 + off);
            }
            uint32_t offB[2];
#pragma unroll
            for (int ntp = 0; ntp < 2; ntp++)
                offB[ntp] = (uint32_t)(rowB[ntp] * 128) + ((gB ^ (uint32_t)swzB[ntp]) << 4);

            {
                uint32_t byh[4][2], byl[4][2];
#pragma unroll
                for (int ntp = 0; ntp < 2; ntp++) {
                    ldsm_x4(byh[2*ntp][0], byh[2*ntp][1], byh[2*ntp+1][0], byh[2*ntp+1][1],
                            bb + 32768 + offB[ntp]);
                    ldsm_x4(byl[2*ntp][0], byl[2*ntp][1], byl[2*ntp+1][0], byl[2*ntp+1][1],
                            bb + 49152 + offB[ntp]);
                }
#pragma unroll
                for (int nt = 0; nt < 4; nt++)
#pragma unroll
                    for (int mt = 0; mt < 4; mt++) {
                        mma_bf16(accY[mt][nt], al[mt], byh[nt][0], byh[nt][1]);
                        mma_bf16(accY[mt][nt], ah[mt], byl[nt][0], byl[nt][1]);
                        mma_bf16(accY[mt][nt], ah[mt], byh[nt][0], byh[nt][1]);
                    }
            }
            {
                uint32_t bgh[4][2], bgl[4][2];
#pragma unroll
                for (int ntp = 0; ntp < 2; ntp++) {
                    ldsm_x4(bgh[2*ntp][0], bgh[2*ntp][1], bgh[2*ntp+1][0], bgh[2*ntp+1][1],
                            bb + 65536 + offB[ntp]);
                    ldsm_x4(bgl[2*ntp][0], bgl[2*ntp][1], bgl[2*ntp+1][0], bgl[2*ntp+1][1],
                            bb + 81920 + offB[ntp]);
                }
#pragma unroll
                for (int nt = 0; nt < 4; nt++)
#pragma unroll
                    for (int mt = 0; mt < 4; mt++) {
                        mma_bf16(accG[mt][nt], al[mt], bgh[nt][0], bgh[nt][1]);
                        mma_bf16(accG[mt][nt], ah[mt], bgl[nt][0], bgl[nt][1]);
                        mma_bf16(accG[mt][nt], ah[mt], bgh[nt][0], bgh[nt][1]);
                    }
            }
        }
        __syncthreads();
    }

    const int ar = lane >> 2;
    const int ac = lane & 3;
#pragma unroll
    for (int mt = 0; mt < 4; mt++) {
#pragma unroll
        for (int nt = 0; nt < 4; nt++) {
            int gr = m0 + wm + 16 * mt + ar;
            int gc = n0 + wn + 8 * nt + 2 * ac;
            float b_y0 = by[gc], b_y1 = by[gc + 1];
            float b_g0 = bg[gc], b_g1 = bg[gc + 1];
            float v00 = tanhf(accY[mt][nt][0] + b_y0) * leaky(accG[mt][nt][0] + b_g0);
            float v01 = tanhf(accY[mt][nt][1] + b_y1) * leaky(accG[mt][nt][1] + b_g1);
            float v10 = tanhf(accY[mt][nt][2] + b_y0) * leaky(accG[mt][nt][2] + b_g0);
            float v11 = tanhf(accY[mt][nt][3] + b_y1) * leaky(accG[mt][nt][3] + b_g1);
            *(float2*)&out[(size_t)gr * LSTM + gc]       = make_float2(v00, v01);
            *(float2*)&out[(size_t)(gr + 8) * LSTM + gc] = make_float2(v10, v11);
        }
    }
#endif
}

// ---------------------------------------------------------------------------
// Kernel 2: attn_v2 (proven 75 us across five rounds)
// ---------------------------------------------------------------------------
#define A2_S    12000
#define A2_BUF  12800
#define A2_BUFW (60 * 132)
#define A2_FLOATS (A2_BUF + 2 * A2_BUFW)

__global__ __launch_bounds__(256)
void attn_v2(const float* __restrict__ qf, const float* __restrict__ hf,
             const float* __restrict__ emb, const float* __restrict__ notpad,
             const float* __restrict__ cms, float* __restrict__ topic) {
    extern __shared__ float sm[];
    const uint32_t smem_base = (uint32_t)__cvta_generic_to_shared(sm);
    const int t = threadIdx.x;
    const int r = blockIdx.x;
    const int b = blockIdx.y;
    const int br = b * NUM_R + r;

    auto load_chunk = [&](int c) {
        const uint32_t bb = smem_base + (A2_BUF + (c & 1) * A2_BUFW) * 4;
        const int kc = c * 128;
#pragma unroll
        for (int i = 0; i < 8; i++) {
            int idx = t + i * 256;
            if (idx < 640) {
                int row = idx >> 5, seg = idx & 31;
                cpasync16(bb + (uint32_t)(row * 528 + seg * 16),
                          qf + (size_t)(b * SL_Q + row) * LSTM + kc + seg * 4);
            } else if (idx < 1920) {
                int j = idx - 640;
                int row = j >> 5, seg = j & 31;
                cpasync16(bb + (uint32_t)((20 + row) * 528 + seg * 16),
                          hf + (size_t)(br * SL_H + row) * LSTM + kc + seg * 4);
            }
        }
        asm volatile("cp.async.commit_group;" ::: "memory");
    };

    {
        const float* esrc = emb + (size_t)br * (SL_H * WE);
        for (int i = t; i < 3000; i += 256)
            cpasync16(smem_base + (uint32_t)(i * 16), esrc + i * 4);
    }
    load_chunk(0);

    const int q2 = t / 20;
    const int h2 = t % 20;
    float acc00 = 0.f, acc01 = 0.f, acc10 = 0.f, acc11 = 0.f;

    for (int c = 0; c < 8; c++) {
        if (c + 1 < 8) {
            load_chunk(c + 1);
            asm volatile("cp.async.wait_group 1;" ::: "memory");
        } else {
            asm volatile("cp.async.wait_group 0;" ::: "memory");
        }
        __syncthreads();
        if (t < 200) {
            const float* base = sm + A2_BUF + (c & 1) * A2_BUFW;
            const float4* q0p = (const float4*)(base + (2 * q2) * 132);
            const float4* q1p = (const float4*)(base + (2 * q2 + 1) * 132);
            const float4* h0p = (const float4*)(base + (20 + 2 * h2) * 132);
            const float4* h1p = (const float4*)(base + (20 + 2 * h2 + 1) * 132);
#pragma unroll 8
            for (int k = 0; k < 32; k++) {
                float4 q0 = q0p[k], q1 = q1p[k];
                float4 h0 = h0p[k], h1 = h1p[k];
                acc00 += q0.x * h0.x + q0.y * h0.y + q0.z * h0.z + q0.w * h0.w;
                acc01 += q0.x * h1.x + q0.y * h1.y + q0.z * h1.z + q0.w * h1.w;
                acc10 += q1.x * h0.x + q1.y * h0.y + q1.z * h0.z + q1.w * h0.w;
                acc11 += q1.x * h1.x + q1.y * h1.y + q1.z * h1.z + q1.w * h1.w;
            }
        }
        __syncthreads();
    }

    float* S = sm + A2_S;
    if (t < 200) {
        S[(2 * q2)     * SL_H + 2 * h2]     = acc00;
        S[(2 * q2)     * SL_H + 2 * h2 + 1] = acc01;
        S[(2 * q2 + 1) * SL_H + 2 * h2]     = acc10;
        S[(2 * q2 + 1) * SL_H + 2 * h2 + 1] = acc11;
    }
    __syncthreads();

    if (t < SL_Q) {
        float mx = -1e30f;
        for (int h = 0; h < SL_H; h++) {
            float m = notpad[(size_t)br * SL_H + h];
            float s = S[t * SL_H + h] * m + (m - 1.0f) * 10000.0f;
            S[t * SL_H + h] = s;
            mx = fmaxf(mx, s);
        }
        float den = 0.f;
        for (int h = 0; h < SL_H; h++) {
            float e = expf(S[t * SL_H + h] - mx);
            S[t * SL_H + h] = e;
            den += e;
        }
        float inv = 1.0f / den;
        for (int h = 0; h < SL_H; h++) S[t * SL_H + h] *= inv;
    }
    __syncthreads();

    const float cmsv = cms[br];
    for (int task = t; task < SL_Q * 75; task += 256) {
        int q = task / 75, eg = task % 75;
        const float* ss = S + q * SL_H;
        float ax = 0.f, ay = 0.f, az = 0.f, aw = 0.f;
#pragma unroll 8
        for (int h = 0; h < SL_H; h++) {
            float a = ss[h];
            float4 e4 = *(const float4*)(sm + h * WE + eg * 4);
            ax += a * e4.x; ay += a * e4.y; az += a * e4.z; aw += a * e4.w;
        }
        float4 o = make_float4(ax * cmsv, ay * cmsv, az * cmsv, aw * cmsv);
        *(float4*)&topic[(size_t)(br * SL_Q + q) * WE + eg * 4] = o;
    }
}

// ---------------------------------------------------------------------------
// Kernel 3: feat = concat(q_embed, sum_r topic)
// ---------------------------------------------------------------------------
__global__ __launch_bounds__(256)
void feat_build(const float* __restrict__ q_embed, const float* __restrict__ topic,
                float* __restrict__ feat) {
    int idx = blockIdx.x * 256 + threadIdx.x;
    int m  = idx / FEATD;
    int e2 = idx % FEATD;
    float v;
    if (e2 < WE) {
        v = q_embed[(size_t)m * WE + e2];
    } else {
        int e = e2 - WE;
        int b = m / SL_Q, q = m % SL_Q;
        v = 0.f;
#pragma unroll
        for (int r = 0; r < NUM_R; r++)
            v += topic[(size_t)((b * NUM_R + r) * SL_Q + q) * WE + e];
    }
    feat[idx] = v;
}

// ---------------------------------------------------------------------------
// Kernel 4: out = sigmoid(feat@Wg + bg) * feat
// ---------------------------------------------------------------------------
#define FBM 64
#define FBN 64
#define FBK 16

__global__ __launch_bounds__(256)
void final_gemm(const float* __restrict__ feat, const float* __restrict__ Wg,
                const float* __restrict__ bg, float* __restrict__ out) {
    __shared__ float Fs[FBM][FBK + 1];
    __shared__ float Bsm[FBK][FBN + 1];

    const int t = threadIdx.x;
    const int ty = t >> 4, tx = t & 15;
    const int m0 = blockIdx.x * FBM;
    const int n0 = blockIdx.y * FBN;

    float acc[4][4];
#pragma unroll
    for (int i = 0; i < 4; i++)
#pragma unroll
        for (int j = 0; j < 4; j++) acc[i][j] = 0.f;

    for (int k0 = 0; k0 < FEATD; k0 += FBK) {
        for (int i = t; i < FBM * FBK; i += 256) {
            int r = i >> 4, c = i & 15;
            int k = k0 + c;
            Fs[r][c] = (k < FEATD) ? feat[(size_t)(m0 + r) * FEATD + k] : 0.f;
        }
        for (int i = t; i < FBK * FBN; i += 256) {
            int r = i >> 6, c = i & 63;
            int k = k0 + r, n = n0 + c;
            Bsm[r][c] = (k < FEATD && n < FEATD) ? Wg[(size_t)k * FEATD + n] : 0.f;
        }
        __syncthreads();
#pragma unroll
        for (int k = 0; k < FBK; k++) {
            float a[4], bb[4];
#pragma unroll
            for (int i = 0; i < 4; i++) a[i]  = Fs[ty * 4 + i][k];
#pragma unroll
            for (int j = 0; j < 4; j++) bb[j] = Bsm[k][tx * 4 + j];
#pragma unroll
            for (int i = 0; i < 4; i++)
#pragma unroll
                for (int j = 0; j < 4; j++) acc[i][j] += a[i] * bb[j];
        }
        __syncthreads();
    }

#pragma unroll
    for (int i = 0; i < 4; i++) {
        int row = m0 + ty * 4 + i;
#pragma unroll
        for (int j = 0; j < 4; j++) {
            int col = n0 + tx * 4 + j;
            if (col < FEATD) {
                float v = acc[i][j] + bg[col];
                float g = 1.0f / (1.0f + expf(-v));
                out[(size_t)row * FEATD + col] = g * feat[(size_t)row * FEATD + col];
            }
        }
    }
}

// ---------------------------------------------------------------------------
// Host launcher
// ---------------------------------------------------------------------------
extern "C" void kernel_launch(void* const* d_in, const int* in_sizes, int n_in,
                              void* d_out, int out_size) {
    const float* q_embed = (const float*)d_in[0];
    const float* q_enc   = (const float*)d_in[1];
    const float* h_embed = (const float*)d_in[2];
    const float* h_enc   = (const float*)d_in[3];
    const float* notpad  = (const float*)d_in[4];
    const float* cms     = (const float*)d_in[5];
    const float* Wq_y = (const float*)d_in[6];
    const float* bq_y = (const float*)d_in[7];
    const float* Wq_g = (const float*)d_in[8];
    const float* bq_g = (const float*)d_in[9];
    const float* Wh_y = (const float*)d_in[10];
    const float* bh_y = (const float*)d_in[11];
    const float* Wh_g = (const float*)d_in[12];
    const float* bh_g = (const float*)d_in[13];
    const float* Wg   = (const float*)d_in[14];
    const float* bg   = (const float*)d_in[15];
    float* out = (float*)d_out;

    float *qf, *hf, *topic, *feat;
    cudaGetSymbolAddress((void**)&qf,    g_qfeat);
    cudaGetSymbolAddress((void**)&hf,    g_hfeat);
    cudaGetSymbolAddress((void**)&topic, g_topic);
    cudaGetSymbolAddress((void**)&feat,  g_feat);

    uint32_t *xq_h, *xq_l, *xh_h, *xh_l;
    uint32_t *wqy_h, *wqy_l, *wqg_h, *wqg_l, *why_h, *why_l, *whg_h, *whg_l;
    cudaGetSymbolAddress((void**)&xq_h, g_xq_h);
    cudaGetSymbolAddress((void**)&xq_l, g_xq_l);
    cudaGetSymbolAddress((void**)&xh_h, g_xh_h);
    cudaGetSymbolAddress((void**)&xh_l, g_xh_l);
    cudaGetSymbolAddress((void**)&wqy_h, g_wqy_h);
    cudaGetSymbolAddress((void**)&wqy_l, g_wqy_l);
    cudaGetSymbolAddress((void**)&wqg_h, g_wqg_h);
    cudaGetSymbolAddress((void**)&wqg_l, g_wqg_l);
    cudaGetSymbolAddress((void**)&why_h, g_why_h);
    cudaGetSymbolAddress((void**)&why_l, g_why_l);
    cudaGetSymbolAddress((void**)&whg_h, g_whg_h);
    cudaGetSymbolAddress((void**)&whg_l, g_whg_l);

    cudaFuncSetAttribute(gated_gemm_all, cudaFuncAttributeMaxDynamicSharedMemorySize,
                         GG_SMEM);
    cudaFuncSetAttribute(attn_v2, cudaFuncAttributeMaxDynamicSharedMemorySize,
                         A2_FLOATS * (int)sizeof(float));

    // 0: fused X splits
    {
        int n4 = (MQ + MH) * BILSTM / 4;
        split_x_all<<<(n4 + 255) / 256, 256>>>(q_enc, xq_h, xq_l, h_enc, xh_h, xh_l);
    }
    // 1: fused transposed W splits
    {
        dim3 wg(BILSTM / 32, LSTM / 32, 4);
        split_wt_all<<<wg, 256>>>(Wq_y, wqy_h, wqy_l, Wq_g, wqg_h, wqg_l,
                                  Wh_y, why_h, why_l, Wh_g, whg_h, whg_l);
    }
    // 2: merged gated transforms (tcgen05 reordered pipeline / legacy fallback)
    gated_gemm_all<<<dim3(LSTM / TBN, 5 + MH / TBM), 256, GG_SMEM>>>(
        xq_h, xq_l, wqy_h, wqy_l, wqg_h, wqg_l, bq_y, bq_g, qf,
        xh_h, xh_l, why_h, why_l, whg_h, whg_l, bh_y, bh_g, hf);

    // 3: attention + topic
    attn_v2<<<dim3(NUM_R, BS), 256, A2_FLOATS * (int)sizeof(float)>>>(
        qf, hf, h_embed, notpad, cms, topic);

    // 4: concat + reduce over r
    feat_build<<<(MQ * FEATD) / 256, 256>>>(q_embed, topic, feat);

    // 5: final gated output
    final_gemm<<<dim3(MQ / FBM, (FEATD + FBN - 1) / FBN), 256>>>(feat, Wg, bg, out);
}

// round 16
// speedup vs baseline: 1.0189x; 1.0189x over previous
#include <cuda_runtime.h>
#include <cuda_bf16.h>
#include <cstdint>

// ---------------------------------------------------------------------------
// Arch dispatch: tcgen05 only on arch/family-specific targets (field-proven)
// ---------------------------------------------------------------------------
#if defined(__CUDA_ARCH_FEAT_SM103_ALL) || defined(__CUDA_ARCH_FEAT_SM100_ALL) || \
    (defined(__CUDA_ARCH_FAMILY_SPECIFIC__) && (__CUDA_ARCH_FAMILY_SPECIFIC__ == 1030 || __CUDA_ARCH_FAMILY_SPECIFIC__ == 1000)) || \
    (defined(__CUDA_ARCH_SPECIFIC__) && (__CUDA_ARCH_SPECIFIC__ == 1030 || __CUDA_ARCH_SPECIFIC__ == 1000))
#define USE_TC 1
#else
#define USE_TC 0
#endif

// ---------------------------------------------------------------------------
// Shapes
// ---------------------------------------------------------------------------
#define BS      32
#define NUM_R   10
#define SL_Q    20
#define SL_H    40
#define WE      300
#define LSTM    1024
#define BILSTM  2048
#define FEATD   600

#define MQ (BS * SL_Q)          // 640
#define MH (BS * NUM_R * SL_H)  // 12800
#define KW (BILSTM / 2)         // 1024 packed bf16x2 words per row

// ---------------------------------------------------------------------------
// Scratch (device globals)
// ---------------------------------------------------------------------------
__device__ float g_qfeat[MQ * LSTM];
__device__ float g_hfeat[MH * LSTM];
__device__ float g_topic[BS * NUM_R * SL_Q * WE];
__device__ float g_feat [MQ * FEATD];

__device__ uint32_t g_xq_h[MQ * KW],  g_xq_l[MQ * KW];
__device__ uint32_t g_xh_h[MH * KW],  g_xh_l[MH * KW];
__device__ uint32_t g_wqy_h[LSTM * KW], g_wqy_l[LSTM * KW];
__device__ uint32_t g_wqg_h[LSTM * KW], g_wqg_l[LSTM * KW];
__device__ uint32_t g_why_h[LSTM * KW], g_why_l[LSTM * KW];
__device__ uint32_t g_whg_h[LSTM * KW], g_whg_l[LSTM * KW];

// ---------------------------------------------------------------------------
// Helpers
// ---------------------------------------------------------------------------
__device__ __forceinline__ float leaky(float x) {
    return x >= 0.f ? x : 0.01f * x;
}

__device__ __forceinline__ void split2(float a, float b, uint32_t& hi, uint32_t& lo) {
    __nv_bfloat16 ha = __float2bfloat16(a);
    __nv_bfloat16 hb = __float2bfloat16(b);
    __nv_bfloat16 la = __float2bfloat16(a - __bfloat162float(ha));
    __nv_bfloat16 lb = __float2bfloat16(b - __bfloat162float(hb));
    union { __nv_bfloat162 v; uint32_t u; } ph, pl;
    ph.v.x = ha; ph.v.y = hb; pl.v.x = la; pl.v.y = lb;
    hi = ph.u; lo = pl.u;
}

__device__ __forceinline__ void cpasync16(uint32_t dst, const void* src) {
    asm volatile("cp.async.cg.shared.global [%0], [%1], 16;"
                 :: "r"(dst), "l"(src) : "memory");
}

__device__ __forceinline__ void mma_bf16(float c[4], const uint32_t a[4],
                                         uint32_t b0, uint32_t b1) {
    asm volatile(
        "mma.sync.aligned.m16n8k16.row.col.f32.bf16.bf16.f32 "
        "{%0,%1,%2,%3},{%4,%5,%6,%7},{%8,%9},{%0,%1,%2,%3};"
        : "+f"(c[0]), "+f"(c[1]), "+f"(c[2]), "+f"(c[3])
        : "r"(a[0]), "r"(a[1]), "r"(a[2]), "r"(a[3]), "r"(b0), "r"(b1));
}

__device__ __forceinline__ void ldsm_x4(uint32_t& r0, uint32_t& r1,
                                        uint32_t& r2, uint32_t& r3, uint32_t addr) {
    asm volatile("ldmatrix.sync.aligned.m8n8.x4.shared.b16 {%0,%1,%2,%3}, [%4];"
                 : "=r"(r0), "=r"(r1), "=r"(r2), "=r"(r3) : "r"(addr));
}

#if USE_TC
__device__ __forceinline__ uint32_t elect_one() {
    uint32_t pred;
    asm volatile("{\n\t.reg .pred p;\n\telect.sync _|p, 0xFFFFFFFF;\n\t"
                 "selp.b32 %0, 1, 0, p;\n\t}" : "=r"(pred));
    return pred;
}
__device__ __forceinline__ void mbar_init(uint32_t mbar, uint32_t cnt) {
    asm volatile("mbarrier.init.shared.b64 [%0], %1;" :: "r"(mbar), "r"(cnt) : "memory");
}
__device__ __forceinline__ void mbar_inval(uint32_t mbar) {
    asm volatile("mbarrier.inval.shared.b64 [%0];" :: "r"(mbar) : "memory");
}
__device__ __forceinline__ void mbar_wait(uint32_t mbar, uint32_t parity) {
    asm volatile(
        "{\n\t.reg .pred P;\n\t"
        "WAIT_%=:\n\t"
        "mbarrier.try_wait.parity.acquire.cta.shared::cta.b64 P, [%0], %1, 0x989680;\n\t"
        "@P bra DONE_%=;\n\t"
        "bra WAIT_%=;\n\t"
        "DONE_%=:\n\t}"
        :: "r"(mbar), "r"(parity) : "memory");
}
// SW64 K-major smem descriptor (layout=4, version=1, SBO=32, LBO=1) —
// constant vendored in ptx_helpers.cuh (SMEM_DESC_BASE_SW64)
__device__ __forceinline__ uint64_t sdesc64(uint32_t addr) {
    return (4ull << 61) | (1ull << 46) | (32ull << 32) | (1ull << 16)
         | ((uint64_t)(addr >> 4) & 0x3FFF);
}
__device__ __forceinline__ void mma_ss(uint32_t d, uint64_t a, uint64_t b,
                                       uint32_t idesc, uint32_t en) {
    asm volatile(
        "{\n\t.reg .pred p;\n\tsetp.ne.u32 p, %4, 0;\n\t"
        "tcgen05.mma.cta_group::1.kind::f16 [%0], %1, %2, %3, {%5, %5, %5, %5}, p;\n\t}"
        :: "r"(d), "l"(a), "l"(b), "r"(idesc), "r"(en), "r"(0u)
        : "memory");
}
__device__ __forceinline__ void ldtm_x32(uint32_t* r, uint32_t a) {
    asm volatile(
        "tcgen05.ld.sync.aligned.32x32b.x32.b32 "
        "{%0,%1,%2,%3,%4,%5,%6,%7,%8,%9,%10,%11,%12,%13,%14,%15,"
        "%16,%17,%18,%19,%20,%21,%22,%23,%24,%25,%26,%27,%28,%29,%30,%31}, [%32];"
        : "=r"(r[0]),  "=r"(r[1]),  "=r"(r[2]),  "=r"(r[3]),
          "=r"(r[4]),  "=r"(r[5]),  "=r"(r[6]),  "=r"(r[7]),
          "=r"(r[8]),  "=r"(r[9]),  "=r"(r[10]), "=r"(r[11]),
          "=r"(r[12]), "=r"(r[13]), "=r"(r[14]), "=r"(r[15]),
          "=r"(r[16]), "=r"(r[17]), "=r"(r[18]), "=r"(r[19]),
          "=r"(r[20]), "=r"(r[21]), "=r"(r[22]), "=r"(r[23]),
          "=r"(r[24]), "=r"(r[25]), "=r"(r[26]), "=r"(r[27]),
          "=r"(r[28]), "=r"(r[29]), "=r"(r[30]), "=r"(r[31])
        : "r"(a));
}
#endif  // USE_TC

// ---------------------------------------------------------------------------
// Precompute (fused): X_q and X_h -> packed kpair bf16 hi/lo words (proven)
// ---------------------------------------------------------------------------
__global__ __launch_bounds__(256)
void split_x_all(const float* __restrict__ xq, uint32_t* __restrict__ qhi,
                 uint32_t* __restrict__ qlo,
                 const float* __restrict__ xh, uint32_t* __restrict__ hhi,
                 uint32_t* __restrict__ hlo) {
    const int n4q = MQ * BILSTM / 4;
    const int n4h = MH * BILSTM / 4;
    int i = blockIdx.x * 256 + threadIdx.x;
    const float* x; uint32_t *hi, *lo; int j;
    if (i < n4q) { x = xq; hi = qhi; lo = qlo; j = i; }
    else if (i < n4q + n4h) { x = xh; hi = hhi; lo = hlo; j = i - n4q; }
    else return;
    float4 v = ((const float4*)x)[j];
    uint32_t h0, l0, h1, l1;
    split2(v.x, v.y, h0, l0);
    split2(v.z, v.w, h1, l1);
    ((uint2*)hi)[j] = make_uint2(h0, h1);
    ((uint2*)lo)[j] = make_uint2(l0, l1);
}

// ---------------------------------------------------------------------------
// Precompute (fused): 4 weights -> transposed packed [1024][KW] hi/lo (proven)
// ---------------------------------------------------------------------------
__global__ __launch_bounds__(256)
void split_wt_all(const float* __restrict__ W0, uint32_t* __restrict__ h0p, uint32_t* __restrict__ l0p,
                  const float* __restrict__ W1, uint32_t* __restrict__ h1p, uint32_t* __restrict__ l1p,
                  const float* __restrict__ W2, uint32_t* __restrict__ h2p, uint32_t* __restrict__ l2p,
                  const float* __restrict__ W3, uint32_t* __restrict__ h3p, uint32_t* __restrict__ l3p) {
    const float* W; uint32_t *thi, *tlo;
    switch (blockIdx.z) {
        case 0:  W = W0; thi = h0p; tlo = l0p; break;
        case 1:  W = W1; thi = h1p; tlo = l1p; break;
        case 2:  W = W2; thi = h2p; tlo = l2p; break;
        default: W = W3; thi = h3p; tlo = l3p; break;
    }
    __shared__ float t[32][33];
    int k0 = blockIdx.x * 32, n0 = blockIdx.y * 32;
    int tx = threadIdx.x & 31, ty = threadIdx.x >> 5;
#pragma unroll
    for (int j = 0; j < 4; j++)
        t[ty + 8 * j][tx] = W[(size_t)(k0 + ty + 8 * j) * LSTM + n0 + tx];
    __syncthreads();
    for (int w = threadIdx.x; w < 512; w += 256) {
        int nn = w >> 4;
        int kp = w & 15;
        uint32_t h, l;
        split2(t[2 * kp][nn], t[2 * kp + 1][nn], h, l);
        size_t o = (size_t)(n0 + nn) * KW + (k0 >> 1) + kp;
        thi[o] = h;
        tlo[o] = l;
    }
}

// ---------------------------------------------------------------------------
// Gated transform: out = tanh(X@Wy+by) * leaky_relu(X@Wg+bg), 3xBF16.
// Path A (tcgen05): M=256 supertile (two 128-row halves vs shared W chunk),
//   K-chunk 32, SW64 smem rows (64B), 4 TMEM accumulators (Y0,G0,Y1,G1).
//   Pipeline ordering = R14's proven one.
// Path B (legacy HMMA fallback): R12 body looped over m-halves.
// Grid (8 n-tiles FAST, 55 m-tiles: 0-4 = q TBM128, 5-54 = h TBM256).
// ---------------------------------------------------------------------------
#define TBN 128
#define TKC2 32
#define NCH2 (BILSTM / TKC2)           // 64
#define RGB 8192                        // region bytes: 128 rows x 64B
#define STG2 (8 * RGB)                  // 65536 per stage
#define SM_CTRL 1024
// fallback needs 2 x 98304; tc needs 2 x 65536 — allocate the max
#define GG_SMEM (SM_CTRL + 2 * 98304)
#define IDESC_GG 0x8200490u

__global__ __launch_bounds__(256, 1)
void gated_gemm_all(const uint32_t* __restrict__ qXh, const uint32_t* __restrict__ qXl,
                    const uint32_t* __restrict__ qWyh, const uint32_t* __restrict__ qWyl,
                    const uint32_t* __restrict__ qWgh, const uint32_t* __restrict__ qWgl,
                    const float* __restrict__ qby, const float* __restrict__ qbg,
                    float* __restrict__ qout,
                    const uint32_t* __restrict__ hXh, const uint32_t* __restrict__ hXl,
                    const uint32_t* __restrict__ hWyh, const uint32_t* __restrict__ hWyl,
                    const uint32_t* __restrict__ hWgh, const uint32_t* __restrict__ hWgl,
                    const float* __restrict__ hby, const float* __restrict__ hbg,
                    float* __restrict__ hout) {
    extern __shared__ char smem[];
    const uint32_t smem_base = (uint32_t)__cvta_generic_to_shared(smem);
    const int tid  = threadIdx.x;
    const int warp = tid >> 5;
    const int lane = tid & 31;
    const int n0 = blockIdx.x * TBN;

    const bool isq = (blockIdx.y < 5);
    const bool two_m = !isq;
    const int m0 = isq ? blockIdx.y * 128 : (blockIdx.y - 5) * 256;
    const uint32_t* Xh  = isq ? qXh  : hXh;
    const uint32_t* Xl  = isq ? qXl  : hXl;
    const uint32_t* Wyh = isq ? qWyh : hWyh;
    const uint32_t* Wyl = isq ? qWyl : hWyl;
    const uint32_t* Wgh = isq ? qWgh : hWgh;
    const uint32_t* Wgl = isq ? qWgl : hWgl;
    const float* by = isq ? qby : hby;
    const float* bg = isq ? qbg : hbg;
    float* out = isq ? qout : hout;

#if USE_TC
    // ---- tc loader: 8 regions x 128 rows x 64B, SW64 swizzle, TKC=32 ----
    const int m1 = two_m ? (m0 + 128) : m0;   // clamp A1 for q tiles
    auto load_chunk = [&](int c) {
        const uint32_t bb = smem_base + SM_CTRL + (uint32_t)(c & 1) * STG2;
        const int kw0 = c * (TKC2 / 2);       // 16 words per chunk-row
#pragma unroll
        for (int i = 0; i < 16; i++) {
            const int reg = i >> 1;
            const int idx = tid + (i & 1) * 256;     // 0..511
            const int row = idx >> 2, seg = idx & 3;
            const uint32_t* s; int rb; uint32_t doff;
            if      (reg == 0) { s = Xh;  rb = m0; doff = 0; }
            else if (reg == 1) { s = Xl;  rb = m0; doff = RGB; }
            else if (reg == 2) { s = Xh;  rb = m1; doff = 2 * RGB; }
            else if (reg == 3) { s = Xl;  rb = m1; doff = 3 * RGB; }
            else if (reg == 4) { s = Wyh; rb = n0; doff = 4 * RGB; }
            else if (reg == 5) { s = Wyl; rb = n0; doff = 5 * RGB; }
            else if (reg == 6) { s = Wgh; rb = n0; doff = 6 * RGB; }
            else               { s = Wgl; rb = n0; doff = 7 * RGB; }
            const void* src = s + (size_t)(rb + row) * KW + kw0 + seg * 4;
            uint32_t bo = (uint32_t)(row * 64 + seg * 16);
            cpasync16(bb + doff + (bo ^ ((bo >> 3) & 0x30)), src);
        }
        asm volatile("cp.async.commit_group;" ::: "memory");
    };

    const uint32_t mb0 = smem_base + 16, mb1 = smem_base + 24;
    if (warp == 0)
        asm volatile("tcgen05.alloc.cta_group::1.sync.aligned.shared::cta.b32 [%0], %1;"
                     :: "r"(smem_base), "r"(512u) : "memory");
    if (tid == 0) { mbar_init(mb0, 1); mbar_init(mb1, 1); }
    __syncthreads();
    uint32_t tmem;
    asm volatile("ld.shared.b32 %0, [%1];" : "=r"(tmem) : "r"(smem_base));
    const uint32_t tY0 = tmem, tG0 = tmem + 128;
    const uint32_t tY1 = tmem + 256, tG1 = tmem + 384;

    int ph0 = 0, ph1 = 0;
    load_chunk(0);
    for (int c = 0; c < NCH2; c++) {
        const int n = c + 1;
        if (n < NCH2) {
            if (n >= 2) {
                if (n & 1) { mbar_wait(mb1, (uint32_t)ph1); ph1 ^= 1; }
                else       { mbar_wait(mb0, (uint32_t)ph0); ph0 ^= 1; }
            }
            load_chunk(n);
            asm volatile("cp.async.wait_group 1;" ::: "memory");
        } else {
            asm volatile("cp.async.wait_group 0;" ::: "memory");
        }
        asm volatile("tcgen05.fence::before_thread_sync;" ::: "memory");
        asm volatile("fence.proxy.async.shared::cta;" ::: "memory");
        __syncthreads();

        if (warp == 0) {
            asm volatile("tcgen05.fence::after_thread_sync;" ::: "memory");
            if (elect_one()) {
                const uint32_t bb = smem_base + SM_CTRL + (uint32_t)(c & 1) * STG2;
                uint64_t dA0h = sdesc64(bb),           dA0l = sdesc64(bb + RGB);
                uint64_t dA1h = sdesc64(bb + 2 * RGB), dA1l = sdesc64(bb + 3 * RGB);
                uint64_t dYh  = sdesc64(bb + 4 * RGB), dYl  = sdesc64(bb + 5 * RGB);
                uint64_t dGh  = sdesc64(bb + 6 * RGB), dGl  = sdesc64(bb + 7 * RGB);
#pragma unroll
                for (int s = 0; s < 2; s++) {
                    uint64_t o = (uint64_t)(s * 2);
                    uint32_t en0 = (c == 0 && s == 0) ? 0u : 1u;
                    mma_ss(tY0, dA0h + o, dYh + o, IDESC_GG, en0);
                    mma_ss(tY0, dA0h + o, dYl + o, IDESC_GG, 1u);
                    mma_ss(tY0, dA0l + o, dYh + o, IDESC_GG, 1u);
                    mma_ss(tG0, dA0h + o, dGh + o, IDESC_GG, en0);
                    mma_ss(tG0, dA0h + o, dGl + o, IDESC_GG, 1u);
                    mma_ss(tG0, dA0l + o, dGh + o, IDESC_GG, 1u);
                    if (two_m) {
                        mma_ss(tY1, dA1h + o, dYh + o, IDESC_GG, en0);
                        mma_ss(tY1, dA1h + o, dYl + o, IDESC_GG, 1u);
                        mma_ss(tY1, dA1l + o, dYh + o, IDESC_GG, 1u);
                        mma_ss(tG1, dA1h + o, dGh + o, IDESC_GG, en0);
                        mma_ss(tG1, dA1h + o, dGl + o, IDESC_GG, 1u);
                        mma_ss(tG1, dA1l + o, dGh + o, IDESC_GG, 1u);
                    }
                }
                asm volatile(
                    "tcgen05.commit.cta_group::1.mbarrier::arrive::one.shared::cluster.b64 [%0];"
                    :: "r"((c & 1) ? mb1 : mb0) : "memory");
            }
        }
    }
    // final commit: chunk 63 -> mb1
    mbar_wait(mb1, (uint32_t)ph1);
    asm volatile("tcgen05.fence::after_thread_sync;" ::: "memory");

    float* ep = (float*)(smem + SM_CTRL);   // 128 x 129 staging (reuses buffers)
    const int nhalf = two_m ? 2 : 1;
    for (int hhf = 0; hhf < nhalf; hhf++) {
        const uint32_t bY = hhf ? tY1 : tY0;
        const uint32_t bG = hhf ? tG1 : tG0;
        if (warp < 4) {
            const int m = warp * 32 + lane;
#pragma unroll
            for (int s = 0; s < 4; s++) {
                uint32_t ry[32], rg[32];
                ldtm_x32(ry, bY + s * 32);
                ldtm_x32(rg, bG + s * 32);
                asm volatile("tcgen05.wait::ld.sync.aligned;" ::: "memory");
#pragma unroll
                for (int cc = 0; cc < 32; cc++) {
                    int nn = n0 + s * 32 + cc;
                    float yv = __uint_as_float(ry[cc]) + by[nn];
                    float gv = __uint_as_float(rg[cc]) + bg[nn];
                    ep[m * 129 + s * 32 + cc] = tanhf(yv) * leaky(gv);
                }
            }
        }
        __syncthreads();
        const int mbase = m0 + hhf * 128;
        for (int i = tid; i < 128 * TBN; i += 256) {
            int row = i >> 7, col = i & 127;
            out[(size_t)(mbase + row) * LSTM + n0 + col] = ep[row * 129 + col];
        }
        __syncthreads();
    }
    if (tid == 0) { mbar_inval(mb0); mbar_inval(mb1); }
    __syncthreads();
    if (warp == 0) {
        asm volatile("tcgen05.relinquish_alloc_permit.cta_group::1.sync.aligned;");
        asm volatile("tcgen05.dealloc.cta_group::1.sync.aligned.b32 %0, %1;"
                     :: "r"(tmem), "r"(512u));
    }
#else
    // ---------------- legacy HMMA fallback (R12 body, looped over halves) --
    const int nhalf = two_m ? 2 : 1;
    for (int mh = 0; mh < nhalf; mh++) {
        const int m0e = m0 + mh * 128;
        auto load_chunk = [&](int c) {
            const uint32_t bb = smem_base + SM_CTRL + (uint32_t)(c & 1) * 98304u;
            const int kw0 = c * 32;   // TKC=64 -> 32 words
#pragma unroll
            for (int i = 0; i < 24; i++) {
                const int reg = i >> 2;
                const int v   = tid + (i & 3) * 256;
                const int row = v >> 3, seg = v & 7;
                const uint32_t* s; int rb; uint32_t doff;
                if      (reg == 0) { s = Xh;  rb = m0e; doff = 0; }
                else if (reg == 1) { s = Xl;  rb = m0e; doff = 16384; }
                else if (reg == 2) { s = Wyh; rb = n0;  doff = 32768; }
                else if (reg == 3) { s = Wyl; rb = n0;  doff = 49152; }
                else if (reg == 4) { s = Wgh; rb = n0;  doff = 65536; }
                else               { s = Wgl; rb = n0;  doff = 81920; }
                const void* src = s + (size_t)(rb + row) * KW + kw0 + seg * 4;
                uint32_t bo = (uint32_t)(row * 128 + seg * 16);
                cpasync16(bb + doff + (bo ^ ((bo >> 3) & 0x70)), src);
            }
            asm volatile("cp.async.commit_group;" ::: "memory");
        };

        const int wm = (warp >> 2) * 64;
        const int wn = (warp & 3) * 32;
        int rowA[4], swzA[4];
#pragma unroll
        for (int mt = 0; mt < 4; mt++) {
            rowA[mt] = wm + 16 * mt + (lane & 15);
            swzA[mt] = rowA[mt] & 7;
        }
        const int kselA = lane >> 4;
        int rowB[2], swzB[2];
#pragma unroll
        for (int ntp = 0; ntp < 2; ntp++) {
            rowB[ntp] = wn + 16 * ntp + (lane & 7) + ((lane & 16) >> 1);
            swzB[ntp] = rowB[ntp] & 7;
        }
        const int kselB = (lane >> 3) & 1;

        float accY[4][4][4] = {};
        float accG[4][4][4] = {};

        load_chunk(0);
        for (int c = 0; c < 32; c++) {
            if (c + 1 < 32) {
                load_chunk(c + 1);
                asm volatile("cp.async.wait_group 1;" ::: "memory");
            } else {
                asm volatile("cp.async.wait_group 0;" ::: "memory");
            }
            __syncthreads();
            const uint32_t bb = smem_base + SM_CTRL + (uint32_t)(c & 1) * 98304u;
#pragma unroll
            for (int ks = 0; ks < 4; ks++) {
                const uint32_t gA = (uint32_t)(2 * ks + kselA);
                const uint32_t gB = (uint32_t)(2 * ks + kselB);
                uint32_t ah[4][4], al[4][4];
#pragma unroll
                for (int mt = 0; mt < 4; mt++) {
                    uint32_t off = (uint32_t)(rowA[mt] * 128) + ((gA ^ (uint32_t)swzA[mt]) << 4);
                    ldsm_x4(ah[mt][0], ah[mt][1], ah[mt][2], ah[mt][3], bb + off);
                    ldsm_x4(al[mt][0], al[mt][1], al[mt][2], al[mt][3], bb + 16384 + off);
                }
                uint32_t offB[2];
#pragma unroll
                for (int ntp = 0; ntp < 2; ntp++)
                    offB[ntp] = (uint32_t)(rowB[ntp] * 128) + ((gB ^ (uint32_t)swzB[ntp]) << 4);
                {
                    uint32_t byh[4][2], byl[4][2];
#pragma unroll
                    for (int ntp = 0; ntp < 2; ntp++) {
                        ldsm_x4(byh[2*ntp][0], byh[2*ntp][1], byh[2*ntp+1][0], byh[2*ntp+1][1],
                                bb + 32768 + offB[ntp]);
                        ldsm_x4(byl[2*ntp][0], byl[2*ntp][1], byl[2*ntp+1][0], byl[2*ntp+1][1],
                                bb + 49152 + offB[ntp]);
                    }
#pragma unroll
                    for (int nt = 0; nt < 4; nt++)
#pragma unroll
                        for (int mt = 0; mt < 4; mt++) {
                            mma_bf16(accY[mt][nt], al[mt], byh[nt][0], byh[nt][1]);
                            mma_bf16(accY[mt][nt], ah[mt], byl[nt][0], byl[nt][1]);
                            mma_bf16(accY[mt][nt], ah[mt], byh[nt][0], byh[nt][1]);
                        }
                }
                {
                    uint32_t bgh[4][2], bgl[4][2];
#pragma unroll
                    for (int ntp = 0; ntp < 2; ntp++) {
                        ldsm_x4(bgh[2*ntp][0], bgh[2*ntp][1], bgh[2*ntp+1][0], bgh[2*ntp+1][1],
                                bb + 65536 + offB[ntp]);
                        ldsm_x4(bgl[2*ntp][0], bgl[2*ntp][1], bgl[2*ntp+1][0], bgl[2*ntp+1][1],
                                bb + 81920 + offB[ntp]);
                    }
#pragma unroll
                    for (int nt = 0; nt < 4; nt++)
#pragma unroll
                        for (int mt = 0; mt < 4; mt++) {
                            mma_bf16(accG[mt][nt], al[mt], bgh[nt][0], bgh[nt][1]);
                            mma_bf16(accG[mt][nt], ah[mt], bgl[nt][0], bgl[nt][1]);
                            mma_bf16(accG[mt][nt], ah[mt], bgh[nt][0], bgh[nt][1]);
                        }
                }
            }
            __syncthreads();
        }

        const int ar = lane >> 2;
        const int ac = lane & 3;
#pragma unroll
        for (int mt = 0; mt < 4; mt++) {
#pragma unroll
            for (int nt = 0; nt < 4; nt++) {
                int gr = m0e + wm + 16 * mt + ar;
                int gc = n0 + wn + 8 * nt + 2 * ac;
                float b_y0 = by[gc], b_y1 = by[gc + 1];
                float b_g0 = bg[gc], b_g1 = bg[gc + 1];
                float v00 = tanhf(accY[mt][nt][0] + b_y0) * leaky(accG[mt][nt][0] + b_g0);
                float v01 = tanhf(accY[mt][nt][1] + b_y1) * leaky(accG[mt][nt][1] + b_g1);
                float v10 = tanhf(accY[mt][nt][2] + b_y0) * leaky(accG[mt][nt][2] + b_g0);
                float v11 = tanhf(accY[mt][nt][3] + b_y1) * leaky(accG[mt][nt][3] + b_g1);
                *(float2*)&out[(size_t)gr * LSTM + gc]       = make_float2(v00, v01);
                *(float2*)&out[(size_t)(gr + 8) * LSTM + gc] = make_float2(v10, v11);
            }
        }
        __syncthreads();
    }
#endif
}

// ---------------------------------------------------------------------------
// Kernel 2: attn_v2 (proven 75 us across five rounds)
// ---------------------------------------------------------------------------
#define A2_S    12000
#define A2_BUF  12800
#define A2_BUFW (60 * 132)
#define A2_FLOATS (A2_BUF + 2 * A2_BUFW)

__global__ __launch_bounds__(256)
void attn_v2(const float* __restrict__ qf, const float* __restrict__ hf,
             const float* __restrict__ emb, const float* __restrict__ notpad,
             const float* __restrict__ cms, float* __restrict__ topic) {
    extern __shared__ float sm[];
    const uint32_t smem_base = (uint32_t)__cvta_generic_to_shared(sm);
    const int t = threadIdx.x;
    const int r = blockIdx.x;
    const int b = blockIdx.y;
    const int br = b * NUM_R + r;

    auto load_chunk = [&](int c) {
        const uint32_t bb = smem_base + (A2_BUF + (c & 1) * A2_BUFW) * 4;
        const int kc = c * 128;
#pragma unroll
        for (int i = 0; i < 8; i++) {
            int idx = t + i * 256;
            if (idx < 640) {
                int row = idx >> 5, seg = idx & 31;
                cpasync16(bb + (uint32_t)(row * 528 + seg * 16),
                          qf + (size_t)(b * SL_Q + row) * LSTM + kc + seg * 4);
            } else if (idx < 1920) {
                int j = idx - 640;
                int row = j >> 5, seg = j & 31;
                cpasync16(bb + (uint32_t)((20 + row) * 528 + seg * 16),
                          hf + (size_t)(br * SL_H + row) * LSTM + kc + seg * 4);
            }
        }
        asm volatile("cp.async.commit_group;" ::: "memory");
    };

    {
        const float* esrc = emb + (size_t)br * (SL_H * WE);
        for (int i = t; i < 3000; i += 256)
            cpasync16(smem_base + (uint32_t)(i * 16), esrc + i * 4);
    }
    load_chunk(0);

    const int q2 = t / 20;
    const int h2 = t % 20;
    float acc00 = 0.f, acc01 = 0.f, acc10 = 0.f, acc11 = 0.f;

    for (int c = 0; c < 8; c++) {
        if (c + 1 < 8) {
            load_chunk(c + 1);
            asm volatile("cp.async.wait_group 1;" ::: "memory");
        } else {
            asm volatile("cp.async.wait_group 0;" ::: "memory");
        }
        __syncthreads();
        if (t < 200) {
            const float* base = sm + A2_BUF + (c & 1) * A2_BUFW;
            const float4* q0p = (const float4*)(base + (2 * q2) * 132);
            const float4* q1p = (const float4*)(base + (2 * q2 + 1) * 132);
            const float4* h0p = (const float4*)(base + (20 + 2 * h2) * 132);
            const float4* h1p = (const float4*)(base + (20 + 2 * h2 + 1) * 132);
#pragma unroll 8
            for (int k = 0; k < 32; k++) {
                float4 q0 = q0p[k], q1 = q1p[k];
                float4 h0 = h0p[k], h1 = h1p[k];
                acc00 += q0.x * h0.x + q0.y * h0.y + q0.z * h0.z + q0.w * h0.w;
                acc01 += q0.x * h1.x + q0.y * h1.y + q0.z * h1.z + q0.w * h1.w;
                acc10 += q1.x * h0.x + q1.y * h0.y + q1.z * h0.z + q1.w * h0.w;
                acc11 += q1.x * h1.x + q1.y * h1.y + q1.z * h1.z + q1.w * h1.w;
            }
        }
        __syncthreads();
    }

    float* S = sm + A2_S;
    if (t < 200) {
        S[(2 * q2)     * SL_H + 2 * h2]     = acc00;
        S[(2 * q2)     * SL_H + 2 * h2 + 1] = acc01;
        S[(2 * q2 + 1) * SL_H + 2 * h2]     = acc10;
        S[(2 * q2 + 1) * SL_H + 2 * h2 + 1] = acc11;
    }
    __syncthreads();

    if (t < SL_Q) {
        float mx = -1e30f;
        for (int h = 0; h < SL_H; h++) {
            float m = notpad[(size_t)br * SL_H + h];
            float s = S[t * SL_H + h] * m + (m - 1.0f) * 10000.0f;
            S[t * SL_H + h] = s;
            mx = fmaxf(mx, s);
        }
        float den = 0.f;
        for (int h = 0; h < SL_H; h++) {
            float e = expf(S[t * SL_H + h] - mx);
            S[t * SL_H + h] = e;
            den += e;
        }
        float inv = 1.0f / den;
        for (int h = 0; h < SL_H; h++) S[t * SL_H + h] *= inv;
    }
    __syncthreads();

    const float cmsv = cms[br];
    for (int task = t; task < SL_Q * 75; task += 256) {
        int q = task / 75, eg = task % 75;
        const float* ss = S + q * SL_H;
        float ax = 0.f, ay = 0.f, az = 0.f, aw = 0.f;
#pragma unroll 8
        for (int h = 0; h < SL_H; h++) {
            float a = ss[h];
            float4 e4 = *(const float4*)(sm + h * WE + eg * 4);
            ax += a * e4.x; ay += a * e4.y; az += a * e4.z; aw += a * e4.w;
        }
        float4 o = make_float4(ax * cmsv, ay * cmsv, az * cmsv, aw * cmsv);
        *(float4*)&topic[(size_t)(br * SL_Q + q) * WE + eg * 4] = o;
    }
}

// ---------------------------------------------------------------------------
// Kernel 3: feat = concat(q_embed, sum_r topic)
// ---------------------------------------------------------------------------
__global__ __launch_bounds__(256)
void feat_build(const float* __restrict__ q_embed, const float* __restrict__ topic,
                float* __restrict__ feat) {
    int idx = blockIdx.x * 256 + threadIdx.x;
    int m  = idx / FEATD;
    int e2 = idx % FEATD;
    float v;
    if (e2 < WE) {
        v = q_embed[(size_t)m * WE + e2];
    } else {
        int e = e2 - WE;
        int b = m / SL_Q, q = m % SL_Q;
        v = 0.f;
#pragma unroll
        for (int r = 0; r < NUM_R; r++)
            v += topic[(size_t)((b * NUM_R + r) * SL_Q + q) * WE + e];
    }
    feat[idx] = v;
}

// ---------------------------------------------------------------------------
// Kernel 4: out = sigmoid(feat@Wg + bg) * feat
// ---------------------------------------------------------------------------
#define FBM 64
#define FBN 64
#define FBK 16

__global__ __launch_bounds__(256)
void final_gemm(const float* __restrict__ feat, const float* __restrict__ Wg,
                const float* __restrict__ bg, float* __restrict__ out) {
    __shared__ float Fs[FBM][FBK + 1];
    __shared__ float Bsm[FBK][FBN + 1];

    const int t = threadIdx.x;
    const int ty = t >> 4, tx = t & 15;
    const int m0 = blockIdx.x * FBM;
    const int n0 = blockIdx.y * FBN;

    float acc[4][4];
#pragma unroll
    for (int i = 0; i < 4; i++)
#pragma unroll
        for (int j = 0; j < 4; j++) acc[i][j] = 0.f;

    for (int k0 = 0; k0 < FEATD; k0 += FBK) {
        for (int i = t; i < FBM * FBK; i += 256) {
            int r = i >> 4, c = i & 15;
            int k = k0 + c;
            Fs[r][c] = (k < FEATD) ? feat[(size_t)(m0 + r) * FEATD + k] : 0.f;
        }
        for (int i = t; i < FBK * FBN; i += 256) {
            int r = i >> 6, c = i & 63;
            int k = k0 + r, n = n0 + c;
            Bsm[r][c] = (k < FEATD && n < FEATD) ? Wg[(size_t)k * FEATD + n] : 0.f;
        }
        __syncthreads();
#pragma unroll
        for (int k = 0; k < FBK; k++) {
            float a[4], bb[4];
#pragma unroll
            for (int i = 0; i < 4; i++) a[i]  = Fs[ty * 4 + i][k];
#pragma unroll
            for (int j = 0; j < 4; j++) bb[j] = Bsm[k][tx * 4 + j];
#pragma unroll
            for (int i = 0; i < 4; i++)
#pragma unroll
                for (int j = 0; j < 4; j++) acc[i][j] += a[i] * bb[j];
        }
        __syncthreads();
    }

#pragma unroll
    for (int i = 0; i < 4; i++) {
        int row = m0 + ty * 4 + i;
#pragma unroll
        for (int j = 0; j < 4; j++) {
            int col = n0 + tx * 4 + j;
            if (col < FEATD) {
                float v = acc[i][j] + bg[col];
                float g = 1.0f / (1.0f + expf(-v));
                out[(size_t)row * FEATD + col] = g * feat[(size_t)row * FEATD + col];
            }
        }
    }
}

// ---------------------------------------------------------------------------
// Host launcher
// ---------------------------------------------------------------------------
extern "C" void kernel_launch(void* const* d_in, const int* in_sizes, int n_in,
                              void* d_out, int out_size) {
    const float* q_embed = (const float*)d_in[0];
    const float* q_enc   = (const float*)d_in[1];
    const float* h_embed = (const float*)d_in[2];
    const float* h_enc   = (const float*)d_in[3];
    const float* notpad  = (const float*)d_in[4];
    const float* cms     = (const float*)d_in[5];
    const float* Wq_y = (const float*)d_in[6];
    const float* bq_y = (const float*)d_in[7];
    const float* Wq_g = (const float*)d_in[8];
    const float* bq_g = (const float*)d_in[9];
    const float* Wh_y = (const float*)d_in[10];
    const float* bh_y = (const float*)d_in[11];
    const float* Wh_g = (const float*)d_in[12];
    const float* bh_g = (const float*)d_in[13];
    const float* Wg   = (const float*)d_in[14];
    const float* bg   = (const float*)d_in[15];
    float* out = (float*)d_out;

    float *qf, *hf, *topic, *feat;
    cudaGetSymbolAddress((void**)&qf,    g_qfeat);
    cudaGetSymbolAddress((void**)&hf,    g_hfeat);
    cudaGetSymbolAddress((void**)&topic, g_topic);
    cudaGetSymbolAddress((void**)&feat,  g_feat);

    uint32_t *xq_h, *xq_l, *xh_h, *xh_l;
    uint32_t *wqy_h, *wqy_l, *wqg_h, *wqg_l, *why_h, *why_l, *whg_h, *whg_l;
    cudaGetSymbolAddress((void**)&xq_h, g_xq_h);
    cudaGetSymbolAddress((void**)&xq_l, g_xq_l);
    cudaGetSymbolAddress((void**)&xh_h, g_xh_h);
    cudaGetSymbolAddress((void**)&xh_l, g_xh_l);
    cudaGetSymbolAddress((void**)&wqy_h, g_wqy_h);
    cudaGetSymbolAddress((void**)&wqy_l, g_wqy_l);
    cudaGetSymbolAddress((void**)&wqg_h, g_wqg_h);
    cudaGetSymbolAddress((void**)&wqg_l, g_wqg_l);
    cudaGetSymbolAddress((void**)&why_h, g_why_h);
    cudaGetSymbolAddress((void**)&why_l, g_why_l);
    cudaGetSymbolAddress((void**)&whg_h, g_whg_h);
    cudaGetSymbolAddress((void**)&whg_l, g_whg_l);

    cudaFuncSetAttribute(gated_gemm_all, cudaFuncAttributeMaxDynamicSharedMemorySize,
                         GG_SMEM);
    cudaFuncSetAttribute(attn_v2, cudaFuncAttributeMaxDynamicSharedMemorySize,
                         A2_FLOATS * (int)sizeof(float));

    // 0: fused X splits
    {
        int n4 = (MQ + MH) * BILSTM / 4;
        split_x_all<<<(n4 + 255) / 256, 256>>>(q_enc, xq_h, xq_l, h_enc, xh_h, xh_l);
    }
    // 1: fused transposed W splits
    {
        dim3 wg(BILSTM / 32, LSTM / 32, 4);
        split_wt_all<<<wg, 256>>>(Wq_y, wqy_h, wqy_l, Wq_g, wqg_h, wqg_l,
                                  Wh_y, why_h, why_l, Wh_g, whg_h, whg_l);
    }
    // 2: merged gated transforms (M=256 supertile tc path / legacy fallback)
    //    grid.y: 0-4 = q (TBM 128), 5-54 = h (TBM 256)
    gated_gemm_all<<<dim3(LSTM / TBN, 5 + MH / 256), 256, GG_SMEM>>>(
        xq_h, xq_l, wqy_h, wqy_l, wqg_h, wqg_l, bq_y, bq_g, qf,
        xh_h, xh_l, why_h, why_l, whg_h, whg_l, bh_y, bh_g, hf);

    // 3: attention + topic
    attn_v2<<<dim3(NUM_R, BS), 256, A2_FLOATS * (int)sizeof(float)>>>(
        qf, hf, h_embed, notpad, cms, topic);

    // 4: concat + reduce over r
    feat_build<<<(MQ * FEATD) / 256, 256>>>(q_embed, topic, feat);

    // 5: final gated output
    final_gemm<<<dim3(MQ / FBM, (FEATD + FBN - 1) / FBN), 256>>>(feat, Wg, bg, out);
}

// round 17
// speedup vs baseline: 1.1543x; 1.1328x over previous
#include <cuda_runtime.h>
#include <cuda_bf16.h>
#include <cstdint>

// ---------------------------------------------------------------------------
// Arch dispatch: tcgen05 only on arch/family-specific targets (field-proven)
// ---------------------------------------------------------------------------
#if defined(__CUDA_ARCH_FEAT_SM103_ALL) || defined(__CUDA_ARCH_FEAT_SM100_ALL) || \
    (defined(__CUDA_ARCH_FAMILY_SPECIFIC__) && (__CUDA_ARCH_FAMILY_SPECIFIC__ == 1030 || __CUDA_ARCH_FAMILY_SPECIFIC__ == 1000)) || \
    (defined(__CUDA_ARCH_SPECIFIC__) && (__CUDA_ARCH_SPECIFIC__ == 1030 || __CUDA_ARCH_SPECIFIC__ == 1000))
#define USE_TC 1
#else
#define USE_TC 0
#endif

// ---------------------------------------------------------------------------
// Shapes
// ---------------------------------------------------------------------------
#define BS      32
#define NUM_R   10
#define SL_Q    20
#define SL_H    40
#define WE      300
#define LSTM    1024
#define BILSTM  2048
#define FEATD   600

#define MQ (BS * SL_Q)          // 640
#define MH (BS * NUM_R * SL_H)  // 12800
#define KW (BILSTM / 2)         // 1024 packed bf16x2 words per row

// ---------------------------------------------------------------------------
// Scratch (device globals)
// ---------------------------------------------------------------------------
__device__ float g_qfeat[MQ * LSTM];
__device__ float g_hfeat[MH * LSTM];
__device__ float g_topic[BS * NUM_R * SL_Q * WE];
__device__ float g_feat [MQ * FEATD];

__device__ uint32_t g_xq_h[MQ * KW],  g_xq_l[MQ * KW];
__device__ uint32_t g_xh_h[MH * KW],  g_xh_l[MH * KW];
__device__ uint32_t g_wqy_h[LSTM * KW], g_wqy_l[LSTM * KW];
__device__ uint32_t g_wqg_h[LSTM * KW], g_wqg_l[LSTM * KW];
__device__ uint32_t g_why_h[LSTM * KW], g_why_l[LSTM * KW];
__device__ uint32_t g_whg_h[LSTM * KW], g_whg_l[LSTM * KW];

// ---------------------------------------------------------------------------
// Helpers
// ---------------------------------------------------------------------------
__device__ __forceinline__ float leaky(float x) {
    return x >= 0.f ? x : 0.01f * x;
}

__device__ __forceinline__ void split2(float a, float b, uint32_t& hi, uint32_t& lo) {
    __nv_bfloat16 ha = __float2bfloat16(a);
    __nv_bfloat16 hb = __float2bfloat16(b);
    __nv_bfloat16 la = __float2bfloat16(a - __bfloat162float(ha));
    __nv_bfloat16 lb = __float2bfloat16(b - __bfloat162float(hb));
    union { __nv_bfloat162 v; uint32_t u; } ph, pl;
    ph.v.x = ha; ph.v.y = hb; pl.v.x = la; pl.v.y = lb;
    hi = ph.u; lo = pl.u;
}

__device__ __forceinline__ void cpasync16(uint32_t dst, const void* src) {
    asm volatile("cp.async.cg.shared.global [%0], [%1], 16;"
                 :: "r"(dst), "l"(src) : "memory");
}

__device__ __forceinline__ void mma_bf16(float c[4], const uint32_t a[4],
                                         uint32_t b0, uint32_t b1) {
    asm volatile(
        "mma.sync.aligned.m16n8k16.row.col.f32.bf16.bf16.f32 "
        "{%0,%1,%2,%3},{%4,%5,%6,%7},{%8,%9},{%0,%1,%2,%3};"
        : "+f"(c[0]), "+f"(c[1]), "+f"(c[2]), "+f"(c[3])
        : "r"(a[0]), "r"(a[1]), "r"(a[2]), "r"(a[3]), "r"(b0), "r"(b1));
}

__device__ __forceinline__ void ldsm_x4(uint32_t& r0, uint32_t& r1,
                                        uint32_t& r2, uint32_t& r3, uint32_t addr) {
    asm volatile("ldmatrix.sync.aligned.m8n8.x4.shared.b16 {%0,%1,%2,%3}, [%4];"
                 : "=r"(r0), "=r"(r1), "=r"(r2), "=r"(r3) : "r"(addr));
}

#if USE_TC
__device__ __forceinline__ uint32_t elect_one() {
    uint32_t pred;
    asm volatile("{\n\t.reg .pred p;\n\telect.sync _|p, 0xFFFFFFFF;\n\t"
                 "selp.b32 %0, 1, 0, p;\n\t}" : "=r"(pred));
    return pred;
}
__device__ __forceinline__ void mbar_init(uint32_t mbar, uint32_t cnt) {
    asm volatile("mbarrier.init.shared.b64 [%0], %1;" :: "r"(mbar), "r"(cnt) : "memory");
}
__device__ __forceinline__ void mbar_inval(uint32_t mbar) {
    asm volatile("mbarrier.inval.shared.b64 [%0];" :: "r"(mbar) : "memory");
}
__device__ __forceinline__ void mbar_wait(uint32_t mbar, uint32_t parity) {
    asm volatile(
        "{\n\t.reg .pred P;\n\t"
        "WAIT_%=:\n\t"
        "mbarrier.try_wait.parity.acquire.cta.shared::cta.b64 P, [%0], %1, 0x989680;\n\t"
        "@P bra DONE_%=;\n\t"
        "bra WAIT_%=;\n\t"
        "DONE_%=:\n\t}"
        :: "r"(mbar), "r"(parity) : "memory");
}
// SW64 K-major smem descriptor (layout=4, version=1, SBO=32, LBO=1) —
// field-verified in R16 (correct rel_err signature)
__device__ __forceinline__ uint64_t sdesc64(uint32_t addr) {
    return (4ull << 61) | (1ull << 46) | (32ull << 32) | (1ull << 16)
         | ((uint64_t)(addr >> 4) & 0x3FFF);
}
__device__ __forceinline__ void mma_ss(uint32_t d, uint64_t a, uint64_t b,
                                       uint32_t idesc, uint32_t en) {
    asm volatile(
        "{\n\t.reg .pred p;\n\tsetp.ne.u32 p, %4, 0;\n\t"
        "tcgen05.mma.cta_group::1.kind::f16 [%0], %1, %2, %3, {%5, %5, %5, %5}, p;\n\t}"
        :: "r"(d), "l"(a), "l"(b), "r"(idesc), "r"(en), "r"(0u)
        : "memory");
}
__device__ __forceinline__ void ldtm_x32(uint32_t* r, uint32_t a) {
    asm volatile(
        "tcgen05.ld.sync.aligned.32x32b.x32.b32 "
        "{%0,%1,%2,%3,%4,%5,%6,%7,%8,%9,%10,%11,%12,%13,%14,%15,"
        "%16,%17,%18,%19,%20,%21,%22,%23,%24,%25,%26,%27,%28,%29,%30,%31}, [%32];"
        : "=r"(r[0]),  "=r"(r[1]),  "=r"(r[2]),  "=r"(r[3]),
          "=r"(r[4]),  "=r"(r[5]),  "=r"(r[6]),  "=r"(r[7]),
          "=r"(r[8]),  "=r"(r[9]),  "=r"(r[10]), "=r"(r[11]),
          "=r"(r[12]), "=r"(r[13]), "=r"(r[14]), "=r"(r[15]),
          "=r"(r[16]), "=r"(r[17]), "=r"(r[18]), "=r"(r[19]),
          "=r"(r[20]), "=r"(r[21]), "=r"(r[22]), "=r"(r[23]),
          "=r"(r[24]), "=r"(r[25]), "=r"(r[26]), "=r"(r[27]),
          "=r"(r[28]), "=r"(r[29]), "=r"(r[30]), "=r"(r[31])
        : "r"(a));
}
#endif  // USE_TC

// ---------------------------------------------------------------------------
// Precompute (fused): X_q and X_h -> packed kpair bf16 hi/lo words (proven)
// ---------------------------------------------------------------------------
__global__ __launch_bounds__(256)
void split_x_all(const float* __restrict__ xq, uint32_t* __restrict__ qhi,
                 uint32_t* __restrict__ qlo,
                 const float* __restrict__ xh, uint32_t* __restrict__ hhi,
                 uint32_t* __restrict__ hlo) {
    const int n4q = MQ * BILSTM / 4;
    const int n4h = MH * BILSTM / 4;
    int i = blockIdx.x * 256 + threadIdx.x;
    const float* x; uint32_t *hi, *lo; int j;
    if (i < n4q) { x = xq; hi = qhi; lo = qlo; j = i; }
    else if (i < n4q + n4h) { x = xh; hi = hhi; lo = hlo; j = i - n4q; }
    else return;
    float4 v = ((const float4*)x)[j];
    uint32_t h0, l0, h1, l1;
    split2(v.x, v.y, h0, l0);
    split2(v.z, v.w, h1, l1);
    ((uint2*)hi)[j] = make_uint2(h0, h1);
    ((uint2*)lo)[j] = make_uint2(l0, l1);
}

// ---------------------------------------------------------------------------
// Precompute (fused): 4 weights -> transposed packed [1024][KW] hi/lo (proven)
// ---------------------------------------------------------------------------
__global__ __launch_bounds__(256)
void split_wt_all(const float* __restrict__ W0, uint32_t* __restrict__ h0p, uint32_t* __restrict__ l0p,
                  const float* __restrict__ W1, uint32_t* __restrict__ h1p, uint32_t* __restrict__ l1p,
                  const float* __restrict__ W2, uint32_t* __restrict__ h2p, uint32_t* __restrict__ l2p,
                  const float* __restrict__ W3, uint32_t* __restrict__ h3p, uint32_t* __restrict__ l3p) {
    const float* W; uint32_t *thi, *tlo;
    switch (blockIdx.z) {
        case 0:  W = W0; thi = h0p; tlo = l0p; break;
        case 1:  W = W1; thi = h1p; tlo = l1p; break;
        case 2:  W = W2; thi = h2p; tlo = l2p; break;
        default: W = W3; thi = h3p; tlo = l3p; break;
    }
    __shared__ float t[32][33];
    int k0 = blockIdx.x * 32, n0 = blockIdx.y * 32;
    int tx = threadIdx.x & 31, ty = threadIdx.x >> 5;
#pragma unroll
    for (int j = 0; j < 4; j++)
        t[ty + 8 * j][tx] = W[(size_t)(k0 + ty + 8 * j) * LSTM + n0 + tx];
    __syncthreads();
    for (int w = threadIdx.x; w < 512; w += 256) {
        int nn = w >> 4;
        int kp = w & 15;
        uint32_t h, l;
        split2(t[2 * kp][nn], t[2 * kp + 1][nn], h, l);
        size_t o = (size_t)(n0 + nn) * KW + (k0 >> 1) + kp;
        thi[o] = h;
        tlo[o] = l;
    }
}

// ---------------------------------------------------------------------------
// Gated transform: out = tanh(X@Wy+by) * leaky_relu(X@Wg+bg), 3xBF16.
// Path A (tcgen05): M=256 supertile, K-chunk 32, SW64 (R16-verified), now with
//   a 3-STAGE pipeline: two loads always in flight; per iteration the thread
//   waits only load(c) (which had a full MMA window) and commit(c-1) (which
//   completes as MMA(c) starts — nearly free). No blocking on a running MMA.
// Path B (legacy HMMA fallback): R12 body looped over m-halves.
// Grid (8 n-tiles FAST, 55 m-tiles: 0-4 = q TBM128, 5-54 = h TBM256).
// ---------------------------------------------------------------------------
#define TBN 128
#define TKC2 32
#define NCH2 (BILSTM / TKC2)           // 64
#define RGB 8192                        // region bytes: 128 rows x 64B
#define STG2 (8 * RGB)                  // 65536 per stage
#define SM_CTRL 1024
// tc: 3 x 65536 = 196608; fallback: 2 x 98304 = 196608 — same footprint
#define GG_SMEM (SM_CTRL + 196608)
#define IDESC_GG 0x8200490u

__global__ __launch_bounds__(256, 1)
void gated_gemm_all(const uint32_t* __restrict__ qXh, const uint32_t* __restrict__ qXl,
                    const uint32_t* __restrict__ qWyh, const uint32_t* __restrict__ qWyl,
                    const uint32_t* __restrict__ qWgh, const uint32_t* __restrict__ qWgl,
                    const float* __restrict__ qby, const float* __restrict__ qbg,
                    float* __restrict__ qout,
                    const uint32_t* __restrict__ hXh, const uint32_t* __restrict__ hXl,
                    const uint32_t* __restrict__ hWyh, const uint32_t* __restrict__ hWyl,
                    const uint32_t* __restrict__ hWgh, const uint32_t* __restrict__ hWgl,
                    const float* __restrict__ hby, const float* __restrict__ hbg,
                    float* __restrict__ hout) {
    extern __shared__ char smem[];
    const uint32_t smem_base = (uint32_t)__cvta_generic_to_shared(smem);
    const int tid  = threadIdx.x;
    const int warp = tid >> 5;
    const int lane = tid & 31;
    const int n0 = blockIdx.x * TBN;

    const bool isq = (blockIdx.y < 5);
    const bool two_m = !isq;
    const int m0 = isq ? blockIdx.y * 128 : (blockIdx.y - 5) * 256;
    const uint32_t* Xh  = isq ? qXh  : hXh;
    const uint32_t* Xl  = isq ? qXl  : hXl;
    const uint32_t* Wyh = isq ? qWyh : hWyh;
    const uint32_t* Wyl = isq ? qWyl : hWyl;
    const uint32_t* Wgh = isq ? qWgh : hWgh;
    const uint32_t* Wgl = isq ? qWgl : hWgl;
    const float* by = isq ? qby : hby;
    const float* bg = isq ? qbg : hbg;
    float* out = isq ? qout : hout;

#if USE_TC
    // ---- tc loader: 8 regions x 128 rows x 64B, SW64 swizzle, 3 stages ----
    const int m1 = two_m ? (m0 + 128) : m0;
    auto load_chunk = [&](int c) {
        const uint32_t bb = smem_base + SM_CTRL + (uint32_t)(c % 3) * STG2;
        const int kw0 = c * (TKC2 / 2);
#pragma unroll
        for (int i = 0; i < 16; i++) {
            const int reg = i >> 1;
            const int idx = tid + (i & 1) * 256;
            const int row = idx >> 2, seg = idx & 3;
            const uint32_t* s; int rb; uint32_t doff;
            if      (reg == 0) { s = Xh;  rb = m0; doff = 0; }
            else if (reg == 1) { s = Xl;  rb = m0; doff = RGB; }
            else if (reg == 2) { s = Xh;  rb = m1; doff = 2 * RGB; }
            else if (reg == 3) { s = Xl;  rb = m1; doff = 3 * RGB; }
            else if (reg == 4) { s = Wyh; rb = n0; doff = 4 * RGB; }
            else if (reg == 5) { s = Wyl; rb = n0; doff = 5 * RGB; }
            else if (reg == 6) { s = Wgh; rb = n0; doff = 6 * RGB; }
            else               { s = Wgl; rb = n0; doff = 7 * RGB; }
            const void* src = s + (size_t)(rb + row) * KW + kw0 + seg * 4;
            uint32_t bo = (uint32_t)(row * 64 + seg * 16);
            cpasync16(bb + doff + (bo ^ ((bo >> 3) & 0x30)), src);
        }
        asm volatile("cp.async.commit_group;" ::: "memory");
    };

    const uint32_t mb[3] = {smem_base + 16, smem_base + 24, smem_base + 32};
    if (warp == 0)
        asm volatile("tcgen05.alloc.cta_group::1.sync.aligned.shared::cta.b32 [%0], %1;"
                     :: "r"(smem_base), "r"(512u) : "memory");
    if (tid == 0) { mbar_init(mb[0], 1); mbar_init(mb[1], 1); mbar_init(mb[2], 1); }
    __syncthreads();
    uint32_t tmem;
    asm volatile("ld.shared.b32 %0, [%1];" : "=r"(tmem) : "r"(smem_base));
    const uint32_t tY0 = tmem, tG0 = tmem + 128;
    const uint32_t tY1 = tmem + 256, tG1 = tmem + 384;

    int ph[3] = {0, 0, 0};
    load_chunk(0);
    load_chunk(1);
    for (int c = 0; c < NCH2; c++) {
        // wait load(c); leave load(c+1) pending if it exists
        if (c + 1 < NCH2) asm volatile("cp.async.wait_group 1;" ::: "memory");
        else              asm volatile("cp.async.wait_group 0;" ::: "memory");
        asm volatile("tcgen05.fence::before_thread_sync;" ::: "memory");
        asm volatile("fence.proxy.async.shared::cta;" ::: "memory");
        __syncthreads();

        if (warp == 0) {
            asm volatile("tcgen05.fence::after_thread_sync;" ::: "memory");
            if (elect_one()) {
                const uint32_t bb = smem_base + SM_CTRL + (uint32_t)(c % 3) * STG2;
                uint64_t dA0h = sdesc64(bb),           dA0l = sdesc64(bb + RGB);
                uint64_t dA1h = sdesc64(bb + 2 * RGB), dA1l = sdesc64(bb + 3 * RGB);
                uint64_t dYh  = sdesc64(bb + 4 * RGB), dYl  = sdesc64(bb + 5 * RGB);
                uint64_t dGh  = sdesc64(bb + 6 * RGB), dGl  = sdesc64(bb + 7 * RGB);
#pragma unroll
                for (int s = 0; s < 2; s++) {
                    uint64_t o = (uint64_t)(s * 2);
                    uint32_t en0 = (c == 0 && s == 0) ? 0u : 1u;
                    mma_ss(tY0, dA0h + o, dYh + o, IDESC_GG, en0);
                    mma_ss(tY0, dA0h + o, dYl + o, IDESC_GG, 1u);
                    mma_ss(tY0, dA0l + o, dYh + o, IDESC_GG, 1u);
                    mma_ss(tG0, dA0h + o, dGh + o, IDESC_GG, en0);
                    mma_ss(tG0, dA0h + o, dGl + o, IDESC_GG, 1u);
                    mma_ss(tG0, dA0l + o, dGh + o, IDESC_GG, 1u);
                    if (two_m) {
                        mma_ss(tY1, dA1h + o, dYh + o, IDESC_GG, en0);
                        mma_ss(tY1, dA1h + o, dYl + o, IDESC_GG, 1u);
                        mma_ss(tY1, dA1l + o, dYh + o, IDESC_GG, 1u);
                        mma_ss(tG1, dA1h + o, dGh + o, IDESC_GG, en0);
                        mma_ss(tG1, dA1h + o, dGl + o, IDESC_GG, 1u);
                        mma_ss(tG1, dA1l + o, dGh + o, IDESC_GG, 1u);
                    }
                }
                asm volatile(
                    "tcgen05.commit.cta_group::1.mbarrier::arrive::one.shared::cluster.b64 [%0];"
                    :: "r"(mb[c % 3]) : "memory");
            }
        }

        // prefetch chunk c+2 into buffer (c+2)%3 — used by MMA(c-1), whose
        // commit completes as MMA(c) begins (in-order queue): wait is ~free
        if (c + 2 < NCH2) {
            if (c >= 1) {
                const int bsel = (c + 2) % 3;   // == (c-1)%3
                mbar_wait(mb[bsel], (uint32_t)ph[bsel]);
                ph[bsel] ^= 1;
            }
            load_chunk(c + 2);   // overlaps MMA(c) and MMA(c+1) issue window
        }
    }
    // final: wait MMA(63)'s commit (mb[0]); in-order queue covers 61/62 too
    mbar_wait(mb[(NCH2 - 1) % 3], (uint32_t)ph[(NCH2 - 1) % 3]);
    asm volatile("tcgen05.fence::after_thread_sync;" ::: "memory");

    float* ep = (float*)(smem + SM_CTRL);   // 128 x 129 staging (reuses buffers)
    const int nhalf = two_m ? 2 : 1;
    for (int hhf = 0; hhf < nhalf; hhf++) {
        const uint32_t bY = hhf ? tY1 : tY0;
        const uint32_t bG = hhf ? tG1 : tG0;
        if (warp < 4) {
            const int m = warp * 32 + lane;
#pragma unroll
            for (int s = 0; s < 4; s++) {
                uint32_t ry[32], rg[32];
                ldtm_x32(ry, bY + s * 32);
                ldtm_x32(rg, bG + s * 32);
                asm volatile("tcgen05.wait::ld.sync.aligned;" ::: "memory");
#pragma unroll
                for (int cc = 0; cc < 32; cc++) {
                    int nn = n0 + s * 32 + cc;
                    float yv = __uint_as_float(ry[cc]) + by[nn];
                    float gv = __uint_as_float(rg[cc]) + bg[nn];
                    ep[m * 129 + s * 32 + cc] = tanhf(yv) * leaky(gv);
                }
            }
        }
        __syncthreads();
        const int mbase = m0 + hhf * 128;
        for (int i = tid; i < 128 * TBN; i += 256) {
            int row = i >> 7, col = i & 127;
            out[(size_t)(mbase + row) * LSTM + n0 + col] = ep[row * 129 + col];
        }
        __syncthreads();
    }
    if (tid == 0) { mbar_inval(mb[0]); mbar_inval(mb[1]); mbar_inval(mb[2]); }
    __syncthreads();
    if (warp == 0) {
        asm volatile("tcgen05.relinquish_alloc_permit.cta_group::1.sync.aligned;");
        asm volatile("tcgen05.dealloc.cta_group::1.sync.aligned.b32 %0, %1;"
                     :: "r"(tmem), "r"(512u));
    }
#else
    // ---------------- legacy HMMA fallback (R12 body, looped over halves) --
    const int nhalf = two_m ? 2 : 1;
    for (int mh = 0; mh < nhalf; mh++) {
        const int m0e = m0 + mh * 128;
        auto load_chunk = [&](int c) {
            const uint32_t bb = smem_base + SM_CTRL + (uint32_t)(c & 1) * 98304u;
            const int kw0 = c * 32;
#pragma unroll
            for (int i = 0; i < 24; i++) {
                const int reg = i >> 2;
                const int v   = tid + (i & 3) * 256;
                const int row = v >> 3, seg = v & 7;
                const uint32_t* s; int rb; uint32_t doff;
                if      (reg == 0) { s = Xh;  rb = m0e; doff = 0; }
                else if (reg == 1) { s = Xl;  rb = m0e; doff = 16384; }
                else if (reg == 2) { s = Wyh; rb = n0;  doff = 32768; }
                else if (reg == 3) { s = Wyl; rb = n0;  doff = 49152; }
                else if (reg == 4) { s = Wgh; rb = n0;  doff = 65536; }
                else               { s = Wgl; rb = n0;  doff = 81920; }
                const void* src = s + (size_t)(rb + row) * KW + kw0 + seg * 4;
                uint32_t bo = (uint32_t)(row * 128 + seg * 16);
                cpasync16(bb + doff + (bo ^ ((bo >> 3) & 0x70)), src);
            }
            asm volatile("cp.async.commit_group;" ::: "memory");
        };

        const int wm = (warp >> 2) * 64;
        const int wn = (warp & 3) * 32;
        int rowA[4], swzA[4];
#pragma unroll
        for (int mt = 0; mt < 4; mt++) {
            rowA[mt] = wm + 16 * mt + (lane & 15);
            swzA[mt] = rowA[mt] & 7;
        }
        const int kselA = lane >> 4;
        int rowB[2], swzB[2];
#pragma unroll
        for (int ntp = 0; ntp < 2; ntp++) {
            rowB[ntp] = wn + 16 * ntp + (lane & 7) + ((lane & 16) >> 1);
            swzB[ntp] = rowB[ntp] & 7;
        }
        const int kselB = (lane >> 3) & 1;

        float accY[4][4][4] = {};
        float accG[4][4][4] = {};

        load_chunk(0);
        for (int c = 0; c < 32; c++) {
            if (c + 1 < 32) {
                load_chunk(c + 1);
                asm volatile("cp.async.wait_group 1;" ::: "memory");
            } else {
                asm volatile("cp.async.wait_group 0;" ::: "memory");
            }
            __syncthreads();
            const uint32_t bb = smem_base + SM_CTRL + (uint32_t)(c & 1) * 98304u;
#pragma unroll
            for (int ks = 0; ks < 4; ks++) {
                const uint32_t gA = (uint32_t)(2 * ks + kselA);
                const uint32_t gB = (uint32_t)(2 * ks + kselB);
                uint32_t ah[4][4], al[4][4];
#pragma unroll
                for (int mt = 0; mt < 4; mt++) {
                    uint32_t off = (uint32_t)(rowA[mt] * 128) + ((gA ^ (uint32_t)swzA[mt]) << 4);
                    ldsm_x4(ah[mt][0], ah[mt][1], ah[mt][2], ah[mt][3], bb + off);
                    ldsm_x4(al[mt][0], al[mt][1], al[mt][2], al[mt][3], bb + 16384 + off);
                }
                uint32_t offB[2];
#pragma unroll
                for (int ntp = 0; ntp < 2; ntp++)
                    offB[ntp] = (uint32_t)(rowB[ntp] * 128) + ((gB ^ (uint32_t)swzB[ntp]) << 4);
                {
                    uint32_t byh[4][2], byl[4][2];
#pragma unroll
                    for (int ntp = 0; ntp < 2; ntp++) {
                        ldsm_x4(byh[2*ntp][0], byh[2*ntp][1], byh[2*ntp+1][0], byh[2*ntp+1][1],
                                bb + 32768 + offB[ntp]);
                        ldsm_x4(byl[2*ntp][0], byl[2*ntp][1], byl[2*ntp+1][0], byl[2*ntp+1][1],
                                bb + 49152 + offB[ntp]);
                    }
#pragma unroll
                    for (int nt = 0; nt < 4; nt++)
#pragma unroll
                        for (int mt = 0; mt < 4; mt++) {
                            mma_bf16(accY[mt][nt], al[mt], byh[nt][0], byh[nt][1]);
                            mma_bf16(accY[mt][nt], ah[mt], byl[nt][0], byl[nt][1]);
                            mma_bf16(accY[mt][nt], ah[mt], byh[nt][0], byh[nt][1]);
                        }
                }
                {
                    uint32_t bgh[4][2], bgl[4][2];
#pragma unroll
                    for (int ntp = 0; ntp < 2; ntp++) {
                        ldsm_x4(bgh[2*ntp][0], bgh[2*ntp][1], bgh[2*ntp+1][0], bgh[2*ntp+1][1],
                                bb + 65536 + offB[ntp]);
                        ldsm_x4(bgl[2*ntp][0], bgl[2*ntp][1], bgl[2*ntp+1][0], bgl[2*ntp+1][1],
                                bb + 81920 + offB[ntp]);
                    }
#pragma unroll
                    for (int nt = 0; nt < 4; nt++)
#pragma unroll
                        for (int mt = 0; mt < 4; mt++) {
                            mma_bf16(accG[mt][nt], al[mt], bgh[nt][0], bgh[nt][1]);
                            mma_bf16(accG[mt][nt], ah[mt], bgl[nt][0], bgl[nt][1]);
                            mma_bf16(accG[mt][nt], ah[mt], bgh[nt][0], bgh[nt][1]);
                        }
                }
            }
            __syncthreads();
        }

        const int ar = lane >> 2;
        const int ac = lane & 3;
#pragma unroll
        for (int mt = 0; mt < 4; mt++) {
#pragma unroll
            for (int nt = 0; nt < 4; nt++) {
                int gr = m0e + wm + 16 * mt + ar;
                int gc = n0 + wn + 8 * nt + 2 * ac;
                float b_y0 = by[gc], b_y1 = by[gc + 1];
                float b_g0 = bg[gc], b_g1 = bg[gc + 1];
                float v00 = tanhf(accY[mt][nt][0] + b_y0) * leaky(accG[mt][nt][0] + b_g0);
                float v01 = tanhf(accY[mt][nt][1] + b_y1) * leaky(accG[mt][nt][1] + b_g1);
                float v10 = tanhf(accY[mt][nt][2] + b_y0) * leaky(accG[mt][nt][2] + b_g0);
                float v11 = tanhf(accY[mt][nt][3] + b_y1) * leaky(accG[mt][nt][3] + b_g1);
                *(float2*)&out[(size_t)gr * LSTM + gc]       = make_float2(v00, v01);
                *(float2*)&out[(size_t)(gr + 8) * LSTM + gc] = make_float2(v10, v11);
            }
        }
        __syncthreads();
    }
#endif
}

// ---------------------------------------------------------------------------
// Kernel 2: attn_v2 (proven 75 us across six rounds)
// ---------------------------------------------------------------------------
#define A2_S    12000
#define A2_BUF  12800
#define A2_BUFW (60 * 132)
#define A2_FLOATS (A2_BUF + 2 * A2_BUFW)

__global__ __launch_bounds__(256)
void attn_v2(const float* __restrict__ qf, const float* __restrict__ hf,
             const float* __restrict__ emb, const float* __restrict__ notpad,
             const float* __restrict__ cms, float* __restrict__ topic) {
    extern __shared__ float sm[];
    const uint32_t smem_base = (uint32_t)__cvta_generic_to_shared(sm);
    const int t = threadIdx.x;
    const int r = blockIdx.x;
    const int b = blockIdx.y;
    const int br = b * NUM_R + r;

    auto load_chunk = [&](int c) {
        const uint32_t bb = smem_base + (A2_BUF + (c & 1) * A2_BUFW) * 4;
        const int kc = c * 128;
#pragma unroll
        for (int i = 0; i < 8; i++) {
            int idx = t + i * 256;
            if (idx < 640) {
                int row = idx >> 5, seg = idx & 31;
                cpasync16(bb + (uint32_t)(row * 528 + seg * 16),
                          qf + (size_t)(b * SL_Q + row) * LSTM + kc + seg * 4);
            } else if (idx < 1920) {
                int j = idx - 640;
                int row = j >> 5, seg = j & 31;
                cpasync16(bb + (uint32_t)((20 + row) * 528 + seg * 16),
                          hf + (size_t)(br * SL_H + row) * LSTM + kc + seg * 4);
            }
        }
        asm volatile("cp.async.commit_group;" ::: "memory");
    };

    {
        const float* esrc = emb + (size_t)br * (SL_H * WE);
        for (int i = t; i < 3000; i += 256)
            cpasync16(smem_base + (uint32_t)(i * 16), esrc + i * 4);
    }
    load_chunk(0);

    const int q2 = t / 20;
    const int h2 = t % 20;
    float acc00 = 0.f, acc01 = 0.f, acc10 = 0.f, acc11 = 0.f;

    for (int c = 0; c < 8; c++) {
        if (c + 1 < 8) {
            load_chunk(c + 1);
            asm volatile("cp.async.wait_group 1;" ::: "memory");
        } else {
            asm volatile("cp.async.wait_group 0;" ::: "memory");
        }
        __syncthreads();
        if (t < 200) {
            const float* base = sm + A2_BUF + (c & 1) * A2_BUFW;
            const float4* q0p = (const float4*)(base + (2 * q2) * 132);
            const float4* q1p = (const float4*)(base + (2 * q2 + 1) * 132);
            const float4* h0p = (const float4*)(base + (20 + 2 * h2) * 132);
            const float4* h1p = (const float4*)(base + (20 + 2 * h2 + 1) * 132);
#pragma unroll 8
            for (int k = 0; k < 32; k++) {
                float4 q0 = q0p[k], q1 = q1p[k];
                float4 h0 = h0p[k], h1 = h1p[k];
                acc00 += q0.x * h0.x + q0.y * h0.y + q0.z * h0.z + q0.w * h0.w;
                acc01 += q0.x * h1.x + q0.y * h1.y + q0.z * h1.z + q0.w * h1.w;
                acc10 += q1.x * h0.x + q1.y * h0.y + q1.z * h0.z + q1.w * h0.w;
                acc11 += q1.x * h1.x + q1.y * h1.y + q1.z * h1.z + q1.w * h1.w;
            }
        }
        __syncthreads();
    }

    float* S = sm + A2_S;
    if (t < 200) {
        S[(2 * q2)     * SL_H + 2 * h2]     = acc00;
        S[(2 * q2)     * SL_H + 2 * h2 + 1] = acc01;
        S[(2 * q2 + 1) * SL_H + 2 * h2]     = acc10;
        S[(2 * q2 + 1) * SL_H + 2 * h2 + 1] = acc11;
    }
    __syncthreads();

    if (t < SL_Q) {
        float mx = -1e30f;
        for (int h = 0; h < SL_H; h++) {
            float m = notpad[(size_t)br * SL_H + h];
            float s = S[t * SL_H + h] * m + (m - 1.0f) * 10000.0f;
            S[t * SL_H + h] = s;
            mx = fmaxf(mx, s);
        }
        float den = 0.f;
        for (int h = 0; h < SL_H; h++) {
            float e = expf(S[t * SL_H + h] - mx);
            S[t * SL_H + h] = e;
            den += e;
        }
        float inv = 1.0f / den;
        for (int h = 0; h < SL_H; h++) S[t * SL_H + h] *= inv;
    }
    __syncthreads();

    const float cmsv = cms[br];
    for (int task = t; task < SL_Q * 75; task += 256) {
        int q = task / 75, eg = task % 75;
        const float* ss = S + q * SL_H;
        float ax = 0.f, ay = 0.f, az = 0.f, aw = 0.f;
#pragma unroll 8
        for (int h = 0; h < SL_H; h++) {
            float a = ss[h];
            float4 e4 = *(const float4*)(sm + h * WE + eg * 4);
            ax += a * e4.x; ay += a * e4.y; az += a * e4.z; aw += a * e4.w;
        }
        float4 o = make_float4(ax * cmsv, ay * cmsv, az * cmsv, aw * cmsv);
        *(float4*)&topic[(size_t)(br * SL_Q + q) * WE + eg * 4] = o;
    }
}

// ---------------------------------------------------------------------------
// Kernel 3: feat = concat(q_embed, sum_r topic)
// ---------------------------------------------------------------------------
__global__ __launch_bounds__(256)
void feat_build(const float* __restrict__ q_embed, const float* __restrict__ topic,
                float* __restrict__ feat) {
    int idx = blockIdx.x * 256 + threadIdx.x;
    int m  = idx / FEATD;
    int e2 = idx % FEATD;
    float v;
    if (e2 < WE) {
        v = q_embed[(size_t)m * WE + e2];
    } else {
        int e = e2 - WE;
        int b = m / SL_Q, q = m % SL_Q;
        v = 0.f;
#pragma unroll
        for (int r = 0; r < NUM_R; r++)
            v += topic[(size_t)((b * NUM_R + r) * SL_Q + q) * WE + e];
    }
    feat[idx] = v;
}

// ---------------------------------------------------------------------------
// Kernel 4: out = sigmoid(feat@Wg + bg) * feat
// ---------------------------------------------------------------------------
#define FBM 64
#define FBN 64
#define FBK 16

__global__ __launch_bounds__(256)
void final_gemm(const float* __restrict__ feat, const float* __restrict__ Wg,
                const float* __restrict__ bg, float* __restrict__ out) {
    __shared__ float Fs[FBM][FBK + 1];
    __shared__ float Bsm[FBK][FBN + 1];

    const int t = threadIdx.x;
    const int ty = t >> 4, tx = t & 15;
    const int m0 = blockIdx.x * FBM;
    const int n0 = blockIdx.y * FBN;

    float acc[4][4];
#pragma unroll
    for (int i = 0; i < 4; i++)
#pragma unroll
        for (int j = 0; j < 4; j++) acc[i][j] = 0.f;

    for (int k0 = 0; k0 < FEATD; k0 += FBK) {
        for (int i = t; i < FBM * FBK; i += 256) {
            int r = i >> 4, c = i & 15;
            int k = k0 + c;
            Fs[r][c] = (k < FEATD) ? feat[(size_t)(m0 + r) * FEATD + k] : 0.f;
        }
        for (int i = t; i < FBK * FBN; i += 256) {
            int r = i >> 6, c = i & 63;
            int k = k0 + r, n = n0 + c;
            Bsm[r][c] = (k < FEATD && n < FEATD) ? Wg[(size_t)k * FEATD + n] : 0.f;
        }
        __syncthreads();
#pragma unroll
        for (int k = 0; k < FBK; k++) {
            float a[4], bb[4];
#pragma unroll
            for (int i = 0; i < 4; i++) a[i]  = Fs[ty * 4 + i][k];
#pragma unroll
            for (int j = 0; j < 4; j++) bb[j] = Bsm[k][tx * 4 + j];
#pragma unroll
            for (int i = 0; i < 4; i++)
#pragma unroll
                for (int j = 0; j < 4; j++) acc[i][j] += a[i] * bb[j];
        }
        __syncthreads();
    }

#pragma unroll
    for (int i = 0; i < 4; i++) {
        int row = m0 + ty * 4 + i;
#pragma unroll
        for (int j = 0; j < 4; j++) {
            int col = n0 + tx * 4 + j;
            if (col < FEATD) {
                float v = acc[i][j] + bg[col];
                float g = 1.0f / (1.0f + expf(-v));
                out[(size_t)row * FEATD + col] = g * feat[(size_t)row * FEATD + col];
            }
        }
    }
}

// ---------------------------------------------------------------------------
// Host launcher
// ---------------------------------------------------------------------------
extern "C" void kernel_launch(void* const* d_in, const int* in_sizes, int n_in,
                              void* d_out, int out_size) {
    const float* q_embed = (const float*)d_in[0];
    const float* q_enc   = (const float*)d_in[1];
    const float* h_embed = (const float*)d_in[2];
    const float* h_enc   = (const float*)d_in[3];
    const float* notpad  = (const float*)d_in[4];
    const float* cms     = (const float*)d_in[5];
    const float* Wq_y = (const float*)d_in[6];
    const float* bq_y = (const float*)d_in[7];
    const float* Wq_g = (const float*)d_in[8];
    const float* bq_g = (const float*)d_in[9];
    const float* Wh_y = (const float*)d_in[10];
    const float* bh_y = (const float*)d_in[11];
    const float* Wh_g = (const float*)d_in[12];
    const float* bh_g = (const float*)d_in[13];
    const float* Wg   = (const float*)d_in[14];
    const float* bg   = (const float*)d_in[15];
    float* out = (float*)d_out;

    float *qf, *hf, *topic, *feat;
    cudaGetSymbolAddress((void**)&qf,    g_qfeat);
    cudaGetSymbolAddress((void**)&hf,    g_hfeat);
    cudaGetSymbolAddress((void**)&topic, g_topic);
    cudaGetSymbolAddress((void**)&feat,  g_feat);

    uint32_t *xq_h, *xq_l, *xh_h, *xh_l;
    uint32_t *wqy_h, *wqy_l, *wqg_h, *wqg_l, *why_h, *why_l, *whg_h, *whg_l;
    cudaGetSymbolAddress((void**)&xq_h, g_xq_h);
    cudaGetSymbolAddress((void**)&xq_l, g_xq_l);
    cudaGetSymbolAddress((void**)&xh_h, g_xh_h);
    cudaGetSymbolAddress((void**)&xh_l, g_xh_l);
    cudaGetSymbolAddress((void**)&wqy_h, g_wqy_h);
    cudaGetSymbolAddress((void**)&wqy_l, g_wqy_l);
    cudaGetSymbolAddress((void**)&wqg_h, g_wqg_h);
    cudaGetSymbolAddress((void**)&wqg_l, g_wqg_l);
    cudaGetSymbolAddress((void**)&why_h, g_why_h);
    cudaGetSymbolAddress((void**)&why_l, g_why_l);
    cudaGetSymbolAddress((void**)&whg_h, g_whg_h);
    cudaGetSymbolAddress((void**)&whg_l, g_whg_l);

    cudaFuncSetAttribute(gated_gemm_all, cudaFuncAttributeMaxDynamicSharedMemorySize,
                         GG_SMEM);
    cudaFuncSetAttribute(attn_v2, cudaFuncAttributeMaxDynamicSharedMemorySize,
                         A2_FLOATS * (int)sizeof(float));

    // 0: fused X splits
    {
        int n4 = (MQ + MH) * BILSTM / 4;
        split_x_all<<<(n4 + 255) / 256, 256>>>(q_enc, xq_h, xq_l, h_enc, xh_h, xh_l);
    }
    // 1: fused transposed W splits
    {
        dim3 wg(BILSTM / 32, LSTM / 32, 4);
        split_wt_all<<<wg, 256>>>(Wq_y, wqy_h, wqy_l, Wq_g, wqg_h, wqg_l,
                                  Wh_y, why_h, why_l, Wh_g, whg_h, whg_l);
    }
    // 2: merged gated transforms (M=256 supertile, 3-stage tc pipeline)
    gated_gemm_all<<<dim3(LSTM / TBN, 5 + MH / 256), 256, GG_SMEM>>>(
        xq_h, xq_l, wqy_h, wqy_l, wqg_h, wqg_l, bq_y, bq_g, qf,
        xh_h, xh_l, why_h, why_l, whg_h, whg_l, bh_y, bh_g, hf);

    // 3: attention + topic
    attn_v2<<<dim3(NUM_R, BS), 256, A2_FLOATS * (int)sizeof(float)>>>(
        qf, hf, h_embed, notpad, cms, topic);

    // 4: concat + reduce over r
    feat_build<<<(MQ * FEATD) / 256, 256>>>(q_embed, topic, feat);

    // 5: final gated output
    final_gemm<<<dim3(MQ / FBM, (FEATD + FBN - 1) / FBN), 256>>>(feat, Wg, bg, out);
}